// round 5
// baseline (speedup 1.0000x reference)
#include <cuda_runtime.h>
#include <cstdint>

// ---------------------------------------------------------------------------
// Problem constants
// ---------------------------------------------------------------------------
namespace {
constexpr int B_   = 4;
constexpr int S_   = 2048;
constexpr int H_   = 768;
constexpr int NH_  = 12;
constexpr int NKV_ = 2;
constexpr int HD_  = 64;
constexpr int GRP_ = NH_ / NKV_;      // 6
constexpr int TOK_ = B_ * S_;         // 8192
constexpr int KVW_ = 2 * NKV_ * HD_;  // 256
}

// ---------------------------------------------------------------------------
// Scratch (static device globals; no allocations allowed)
// ---------------------------------------------------------------------------
__device__ float g_q  [TOK_ * H_];    // [TOK, 768]
__device__ float g_kv [TOK_ * KVW_];  // [TOK, 256]  (K | V per kv-head)
__device__ float g_att[TOK_ * H_];    // [TOK, 768]

// ---------------------------------------------------------------------------
// helpers
// ---------------------------------------------------------------------------
__device__ __forceinline__ uint32_t f2tf(float x) {
    uint32_t r;
    asm("cvt.rna.tf32.f32 %0, %1;" : "=r"(r) : "f"(x));
    return r;
}

__device__ __forceinline__ void mma_tf32(float c[4], const uint32_t a[4],
                                         const uint32_t b[2]) {
    asm volatile(
        "mma.sync.aligned.m16n8k8.row.col.f32.tf32.tf32.f32 "
        "{%0,%1,%2,%3}, {%4,%5,%6,%7}, {%8,%9}, {%0,%1,%2,%3};\n"
        : "+f"(c[0]), "+f"(c[1]), "+f"(c[2]), "+f"(c[3])
        : "r"(a[0]), "r"(a[1]), "r"(a[2]), "r"(a[3]), "r"(b[0]), "r"(b[1]));
}

__device__ __forceinline__ void cp_async16(void* smem_dst, const void* gmem_src) {
    uint32_t sa = (uint32_t)__cvta_generic_to_shared(smem_dst);
    asm volatile("cp.async.ca.shared.global [%0], [%1], 16;\n"
                 :: "r"(sa), "l"(gmem_src));
}
__device__ __forceinline__ void cp_commit() {
    asm volatile("cp.async.commit_group;\n");
}
template <int N>
__device__ __forceinline__ void cp_wait() {
    asm volatile("cp.async.wait_group %0;\n" :: "n"(N));
}

// ---------------------------------------------------------------------------
// tf32 GEMM: C[M,N] = A[M,K] * B[N,K]^T (row-major, K contiguous).
// 128x128 tile, BK=16, 128 threads / 4 warps, warp tile 64x64.
// ---------------------------------------------------------------------------
__global__ __launch_bounds__(128, 2) void gemm_tf32(
    const float* __restrict__ A, const float* __restrict__ Bm,
    float* __restrict__ C, int M, int N, int K)
{
    __shared__ float As[2][128][20];
    __shared__ float Bs[2][128][20];

    const int tid  = threadIdx.x;
    const int lane = tid & 31;
    const int warp = tid >> 5;
    const int wm   = (warp >> 1) * 64;
    const int wn   = (warp & 1) * 64;
    const int bm   = blockIdx.y * 128;
    const int bn   = blockIdx.x * 128;
    const int qr   = lane >> 2;
    const int qc   = lane & 3;

    float acc[4][8][4];
#pragma unroll
    for (int mt = 0; mt < 4; mt++)
#pragma unroll
        for (int nt = 0; nt < 8; nt++)
#pragma unroll
            for (int i = 0; i < 4; i++) acc[mt][nt][i] = 0.0f;

    const float* Abase = A  + (size_t)bm * K;
    const float* Bbase = Bm + (size_t)bn * K;

    auto stage = [&](int buf, int kb) {
        const float* Ab = Abase + kb * 16;
        const float* Bb = Bbase + kb * 16;
#pragma unroll
        for (int u = 0; u < 4; u++) {
            const int id = tid + u * 128;      // float4 id 0..511
            const int r  = id >> 2;
            const int c4 = (id & 3) * 4;
            cp_async16(&As[buf][r][c4], Ab + (size_t)r * K + c4);
            cp_async16(&Bs[buf][r][c4], Bb + (size_t)r * K + c4);
        }
    };

    const int nkb = K / 16;
    stage(0, 0);
    cp_commit();

    for (int kb = 0; kb < nkb; kb++) {
        __syncthreads();
        if (kb + 1 < nkb) stage((kb + 1) & 1, kb + 1);
        cp_commit();
        cp_wait<1>();
        __syncthreads();

        const int buf = kb & 1;
#pragma unroll
        for (int kk = 0; kk < 2; kk++) {
            const int k0 = kk * 8 + qc;
            uint32_t af[4][4], bf[8][2];
#pragma unroll
            for (int mt = 0; mt < 4; mt++) {
                const int m = wm + mt * 16 + qr;
                af[mt][0] = f2tf(As[buf][m][k0]);
                af[mt][1] = f2tf(As[buf][m + 8][k0]);
                af[mt][2] = f2tf(As[buf][m][k0 + 4]);
                af[mt][3] = f2tf(As[buf][m + 8][k0 + 4]);
            }
#pragma unroll
            for (int nt = 0; nt < 8; nt++) {
                const int n = wn + nt * 8 + qr;
                bf[nt][0] = f2tf(Bs[buf][n][k0]);
                bf[nt][1] = f2tf(Bs[buf][n][k0 + 4]);
            }
#pragma unroll
            for (int mt = 0; mt < 4; mt++)
#pragma unroll
                for (int nt = 0; nt < 8; nt++)
                    mma_tf32(acc[mt][nt], af[mt], bf[nt]);
        }
    }

#pragma unroll
    for (int mt = 0; mt < 4; mt++) {
        const int m = bm + wm + mt * 16 + qr;
#pragma unroll
        for (int nt = 0; nt < 8; nt++) {
            const int n = bn + wn + nt * 8 + qc * 2;
            *(float2*)&C[(size_t)m * N + n] =
                make_float2(acc[mt][nt][0], acc[mt][nt][1]);
            *(float2*)&C[(size_t)(m + 8) * N + n] =
                make_float2(acc[mt][nt][2], acc[mt][nt][3]);
        }
    }
}

// ---------------------------------------------------------------------------
// RoPE in-place on Q and the K half of KV
// ---------------------------------------------------------------------------
__global__ void rope_kernel(float* __restrict__ q, float* __restrict__ kv)
{
    const int NQ = TOK_ * NH_  * 32;
    const int NK = TOK_ * NKV_ * 32;
    const int i = blockIdx.x * blockDim.x + threadIdx.x;
    if (i >= NQ + NK) return;

    float* base;
    int t, p;
    if (i < NQ) {
        t = i / (NH_ * 32);
        const int r = i % (NH_ * 32);
        const int h = r / 32;
        p = r & 31;
        base = q + (size_t)t * H_ + h * HD_;
    } else {
        const int j = i - NQ;
        t = j / (NKV_ * 32);
        const int r = j % (NKV_ * 32);
        const int h = r / 32;
        p = r & 31;
        base = kv + (size_t)t * KVW_ + h * HD_;
    }
    const int s = t & (S_ - 1);
    const float inv = exp2f(-(float)p * 0.41524101186092029f);
    const float ang = (float)s * inv;
    float sn, c;
    __sincosf(ang, &sn, &c);
    const float x0 = base[p], x1 = base[p + 32];
    base[p]      = x0 * c - x1 * sn;
    base[p + 32] = x1 * c + x0 * sn;
}

// ---------------------------------------------------------------------------
// Causal flash attention, tf32 MMA, 128-query block, 4 warps, 32 rows/warp.
// R5: Q fragments live in smem (LDS.128 reload), 32-key softmax chunks
// (sf 64->32 regs), V staged as raw f32 bits (mma truncates). Dynamic smem:
//   Ks 64x68 (17408 B) | Vs 64x68 (17408 B) | Qs 4*8*2*32 uint4 (32768 B)
// ---------------------------------------------------------------------------
constexpr int FL_SMEM = 17408 + 17408 + 32768;   // 67584 B

__global__ __launch_bounds__(128, 3) void flash_mma(
    const float* __restrict__ Q, const float* __restrict__ KV,
    float* __restrict__ O)
{
    extern __shared__ char smem[];
    uint32_t (*Ks)[68] = (uint32_t(*)[68])(smem);
    uint32_t (*Vs)[68] = (uint32_t(*)[68])(smem + 17408);
    uint4*    Qs       = (uint4*)(smem + 34816);

    const int tid  = threadIdx.x;
    const int lane = tid & 31;
    const int warp = tid >> 5;
    const int qr   = lane >> 2;
    const int qc   = lane & 3;
    const int bh   = blockIdx.y;
    const int b    = bh / NH_;
    const int h    = bh % NH_;
    const int g    = h / GRP_;
    const int m0   = ((int)gridDim.x - 1 - (int)blockIdx.x) * 128;  // heavy first
    const int wrow = warp * 32;

    // ---- stage Q (scaled by log2e/8, RNA tf32) through Ks/Vs ----
    const float qs = 0.125f * 1.44269504088896341f;
    for (int i = tid; i < 128 * 16; i += 128) {
        const int r  = i >> 4;
        const int d4 = (i & 15) * 4;
        const float* qp = Q + (size_t)(b * S_ + m0 + r) * H_ + h * HD_ + d4;
        float4 v = *(const float4*)qp;
        uint32_t* dst = (r < 64) ? &Ks[r][d4] : &Vs[r - 64][d4];
        *(uint4*)dst = make_uint4(f2tf(v.x * qs), f2tf(v.y * qs),
                                  f2tf(v.z * qs), f2tf(v.w * qs));
    }
    __syncthreads();

    // ---- build Q fragments, park them in Qs (one uint4 per (kk,mt)) ----
    {
        uint4* Qw = Qs + (warp * 16) * 32 + lane;
#pragma unroll
        for (int mt = 0; mt < 2; mt++) {
            const int rbase = wrow + mt * 16;
#pragma unroll
            for (int kk = 0; kk < 8; kk++) {
                const int k = kk * 8 + qc;
                uint4 f;
                if (rbase < 64) {
                    f.x = Ks[rbase + qr][k];
                    f.y = Ks[rbase + qr + 8][k];
                    f.z = Ks[rbase + qr][k + 4];
                    f.w = Ks[rbase + qr + 8][k + 4];
                } else {
                    f.x = Vs[rbase - 64 + qr][k];
                    f.y = Vs[rbase - 64 + qr + 8][k];
                    f.z = Vs[rbase - 64 + qr][k + 4];
                    f.w = Vs[rbase - 64 + qr + 8][k + 4];
                }
                Qw[(kk * 2 + mt) * 32] = f;
            }
        }
    }

    float of[2][8][4];
#pragma unroll
    for (int mt = 0; mt < 2; mt++)
#pragma unroll
        for (int dt = 0; dt < 8; dt++)
#pragma unroll
            for (int i = 0; i < 4; i++) of[mt][dt][i] = 0.0f;
    float m_run[2][2] = {{-1e30f, -1e30f}, {-1e30f, -1e30f}};
    float l_run[2][2] = {{0.0f, 0.0f}, {0.0f, 0.0f}};

    const size_t kvbase = (size_t)b * S_ * KVW_ + g * HD_;
    const int ntiles = m0 / 64 + 2;
    const uint4* Qw = Qs + (warp * 16) * 32 + lane;

    for (int kt = 0; kt < ntiles; kt++) {
        const int k0 = kt * 64;
        __syncthreads();
        for (int i = tid; i < 64 * 16; i += 128) {
            const int r  = i >> 4;
            const int d4 = (i & 15) * 4;
            const float* kp = KV + kvbase + (size_t)(k0 + r) * KVW_ + d4;
            float4 k4 = *(const float4*)kp;
            uint4  v4 = *(const uint4*)(kp + 128);   // raw f32 bits (mma truncates)
            *(uint4*)&Ks[r][d4] = make_uint4(f2tf(k4.x), f2tf(k4.y),
                                             f2tf(k4.z), f2tf(k4.w));
            *(uint4*)&Vs[r][d4] = v4;
        }
        __syncthreads();

        if (k0 > m0 + wrow + 31) continue;   // warp fully above the diagonal

        // ---- two 32-key chunks ----
#pragma unroll
        for (int ch = 0; ch < 2; ch++) {
            const int k0c = k0 + ch * 32;
            if (k0c > m0 + wrow + 31) break;

            // S = Q K^T for this chunk (32x32 rows x keys per warp)
            float sf[2][4][4];
#pragma unroll
            for (int mt = 0; mt < 2; mt++)
#pragma unroll
                for (int nt = 0; nt < 4; nt++)
#pragma unroll
                    for (int i = 0; i < 4; i++) sf[mt][nt][i] = 0.0f;

#pragma unroll
            for (int kk = 0; kk < 8; kk++) {
                uint4 qa = Qw[(kk * 2 + 0) * 32];
                uint4 qb = Qw[(kk * 2 + 1) * 32];
                const uint32_t af0[4] = {qa.x, qa.y, qa.z, qa.w};
                const uint32_t af1[4] = {qb.x, qb.y, qb.z, qb.w};
                uint32_t bfr[4][2];
#pragma unroll
                for (int nt = 0; nt < 4; nt++) {
                    const int n = ch * 32 + nt * 8 + qr;
                    bfr[nt][0] = Ks[n][kk * 8 + qc];
                    bfr[nt][1] = Ks[n][kk * 8 + qc + 4];
                }
#pragma unroll
                for (int nt = 0; nt < 4; nt++) {
                    mma_tf32(sf[0][nt], af0, bfr[nt]);
                    mma_tf32(sf[1][nt], af1, bfr[nt]);
                }
            }

            // causal mask (chunk overlapping the diagonal)
            if (k0c + 31 > m0 + wrow) {
#pragma unroll
                for (int mt = 0; mt < 2; mt++) {
                    const int r0 = m0 + wrow + mt * 16 + qr;
#pragma unroll
                    for (int nt = 0; nt < 4; nt++) {
                        const int cL = k0c + nt * 8 + qc * 2;
                        if (cL     > r0)     sf[mt][nt][0] = -1e30f;
                        if (cL + 1 > r0)     sf[mt][nt][1] = -1e30f;
                        if (cL     > r0 + 8) sf[mt][nt][2] = -1e30f;
                        if (cL + 1 > r0 + 8) sf[mt][nt][3] = -1e30f;
                    }
                }
            }

            // online softmax (exp2 domain); tf32 P bits stored in place
#pragma unroll
            for (int mt = 0; mt < 2; mt++) {
                float tm0 = -1e30f, tm1 = -1e30f;
#pragma unroll
                for (int nt = 0; nt < 4; nt++) {
                    tm0 = fmaxf(tm0, fmaxf(sf[mt][nt][0], sf[mt][nt][1]));
                    tm1 = fmaxf(tm1, fmaxf(sf[mt][nt][2], sf[mt][nt][3]));
                }
                tm0 = fmaxf(tm0, __shfl_xor_sync(0xffffffffu, tm0, 1));
                tm0 = fmaxf(tm0, __shfl_xor_sync(0xffffffffu, tm0, 2));
                tm1 = fmaxf(tm1, __shfl_xor_sync(0xffffffffu, tm1, 1));
                tm1 = fmaxf(tm1, __shfl_xor_sync(0xffffffffu, tm1, 2));

                const float mn0 = fmaxf(m_run[mt][0], tm0);
                const float mn1 = fmaxf(m_run[mt][1], tm1);
                const float cor0 = exp2f(m_run[mt][0] - mn0);
                const float cor1 = exp2f(m_run[mt][1] - mn1);
                m_run[mt][0] = mn0; m_run[mt][1] = mn1;

                float rs0 = 0.0f, rs1 = 0.0f;
#pragma unroll
                for (int nt = 0; nt < 4; nt++) {
                    const float p0 = exp2f(sf[mt][nt][0] - mn0);
                    const float p1 = exp2f(sf[mt][nt][1] - mn0);
                    const float p2 = exp2f(sf[mt][nt][2] - mn1);
                    const float p3 = exp2f(sf[mt][nt][3] - mn1);
                    rs0 += p0 + p1;
                    rs1 += p2 + p3;
                    sf[mt][nt][0] = __uint_as_float(f2tf(p0));
                    sf[mt][nt][1] = __uint_as_float(f2tf(p1));
                    sf[mt][nt][2] = __uint_as_float(f2tf(p2));
                    sf[mt][nt][3] = __uint_as_float(f2tf(p3));
                }
                rs0 += __shfl_xor_sync(0xffffffffu, rs0, 1);
                rs0 += __shfl_xor_sync(0xffffffffu, rs0, 2);
                rs1 += __shfl_xor_sync(0xffffffffu, rs1, 1);
                rs1 += __shfl_xor_sync(0xffffffffu, rs1, 2);
                l_run[mt][0] = l_run[mt][0] * cor0 + rs0;
                l_run[mt][1] = l_run[mt][1] * cor1 + rs1;
#pragma unroll
                for (int dt = 0; dt < 8; dt++) {
                    of[mt][dt][0] *= cor0; of[mt][dt][1] *= cor0;
                    of[mt][dt][2] *= cor1; of[mt][dt][3] *= cor1;
                }
            }

            // O += P V  (S C-frag IS the PV A-frag; key-permuted V rows)
#pragma unroll
            for (int kk2 = 0; kk2 < 4; kk2++) {
                uint32_t af[2][4];
#pragma unroll
                for (int mt = 0; mt < 2; mt++) {
                    af[mt][0] = __float_as_uint(sf[mt][kk2][0]);
                    af[mt][1] = __float_as_uint(sf[mt][kk2][2]);
                    af[mt][2] = __float_as_uint(sf[mt][kk2][1]);
                    af[mt][3] = __float_as_uint(sf[mt][kk2][3]);
                }
                const int vrow = ch * 32 + kk2 * 8 + 2 * qc;
#pragma unroll
                for (int dh = 0; dh < 2; dh++) {
                    uint32_t vb[4][2];
#pragma unroll
                    for (int dt = 0; dt < 4; dt++) {
                        const int d = (dh * 4 + dt) * 8 + qr;
                        vb[dt][0] = Vs[vrow][d];
                        vb[dt][1] = Vs[vrow + 1][d];
                    }
#pragma unroll
                    for (int mt = 0; mt < 2; mt++)
#pragma unroll
                        for (int dt = 0; dt < 4; dt++)
                            mma_tf32(of[mt][dh * 4 + dt], af[mt], vb[dt]);
                }
            }
        }
    }

    // ---- epilogue ----
#pragma unroll
    for (int mt = 0; mt < 2; mt++) {
        const float inv0 = 1.0f / l_run[mt][0];
        const float inv1 = 1.0f / l_run[mt][1];
        const int r0 = m0 + wrow + mt * 16 + qr;
#pragma unroll
        for (int dt = 0; dt < 8; dt++) {
            const int col = h * HD_ + dt * 8 + qc * 2;
            float* o0 = O + (size_t)(b * S_ + r0) * H_ + col;
            float* o1 = O + (size_t)(b * S_ + r0 + 8) * H_ + col;
            *(float2*)o0 = make_float2(of[mt][dt][0] * inv0, of[mt][dt][1] * inv0);
            *(float2*)o1 = make_float2(of[mt][dt][2] * inv1, of[mt][dt][3] * inv1);
        }
    }
}

// ---------------------------------------------------------------------------
// Launch
// ---------------------------------------------------------------------------
extern "C" void kernel_launch(void* const* d_in, const int* in_sizes, int n_in,
                              void* d_out, int out_size)
{
    const float* x   = (const float*)d_in[0];
    const float* wq  = (const float*)d_in[1];
    const float* wkv = (const float*)d_in[2];
    const float* wo  = (const float*)d_in[3];
    float* out = (float*)d_out;

    float *q, *kv, *att;
    cudaGetSymbolAddress((void**)&q,   g_q);
    cudaGetSymbolAddress((void**)&kv,  g_kv);
    cudaGetSymbolAddress((void**)&att, g_att);

    static bool attr_set = false;
    if (!attr_set) {
        cudaFuncSetAttribute(flash_mma,
                             cudaFuncAttributeMaxDynamicSharedMemorySize,
                             FL_SMEM);
        attr_set = true;
    }

    gemm_tf32<<<dim3(H_ / 128, TOK_ / 128), 128>>>(x, wq, q, TOK_, H_, H_);
    gemm_tf32<<<dim3(KVW_ / 128, TOK_ / 128), 128>>>(x, wkv, kv, TOK_, KVW_, H_);

    const int nrope = TOK_ * (NH_ + NKV_) * 32;
    rope_kernel<<<(nrope + 255) / 256, 256>>>(q, kv);

    flash_mma<<<dim3(S_ / 128, B_ * NH_), 128, FL_SMEM>>>(q, kv, att);

    gemm_tf32<<<dim3(H_ / 128, TOK_ / 128), 128>>>(att, wo, out, TOK_, H_, H_);
}

// round 6
// speedup vs baseline: 1.1133x; 1.1133x over previous
#include <cuda_runtime.h>
#include <cstdint>

// ---------------------------------------------------------------------------
// Problem constants
// ---------------------------------------------------------------------------
namespace {
constexpr int B_   = 4;
constexpr int S_   = 2048;
constexpr int H_   = 768;
constexpr int NH_  = 12;
constexpr int NKV_ = 2;
constexpr int HD_  = 64;
constexpr int GRP_ = NH_ / NKV_;      // 6
constexpr int TOK_ = B_ * S_;         // 8192
constexpr int KVW_ = 2 * NKV_ * HD_;  // 256
}

// ---------------------------------------------------------------------------
// Scratch (static device globals; no allocations allowed)
// ---------------------------------------------------------------------------
__device__ float g_q  [TOK_ * H_];    // [TOK, 768]
__device__ float g_kv [TOK_ * KVW_];  // [TOK, 256]  (K | V per kv-head)
__device__ float g_att[TOK_ * H_];    // [TOK, 768]

// ---------------------------------------------------------------------------
// helpers
// ---------------------------------------------------------------------------
__device__ __forceinline__ uint32_t f2tf(float x) {
    uint32_t r;
    asm("cvt.rna.tf32.f32 %0, %1;" : "=r"(r) : "f"(x));
    return r;
}

__device__ __forceinline__ void mma_tf32(float c[4], const uint32_t a[4],
                                         uint32_t b0, uint32_t b1) {
    asm volatile(
        "mma.sync.aligned.m16n8k8.row.col.f32.tf32.tf32.f32 "
        "{%0,%1,%2,%3}, {%4,%5,%6,%7}, {%8,%9}, {%0,%1,%2,%3};\n"
        : "+f"(c[0]), "+f"(c[1]), "+f"(c[2]), "+f"(c[3])
        : "r"(a[0]), "r"(a[1]), "r"(a[2]), "r"(a[3]), "r"(b0), "r"(b1));
}

__device__ __forceinline__ void cp_async16(void* smem_dst, const void* gmem_src) {
    uint32_t sa = (uint32_t)__cvta_generic_to_shared(smem_dst);
    asm volatile("cp.async.ca.shared.global [%0], [%1], 16;\n"
                 :: "r"(sa), "l"(gmem_src));
}
__device__ __forceinline__ void cp_commit() {
    asm volatile("cp.async.commit_group;\n");
}
template <int N>
__device__ __forceinline__ void cp_wait() {
    asm volatile("cp.async.wait_group %0;\n" :: "n"(N));
}

// ---------------------------------------------------------------------------
// tf32 GEMM: C[M,N] = A[M,K] * B[N,K]^T (row-major, K contiguous).
// 128x128 tile, BK=16, 128 threads / 4 warps, warp tile 64x64.
// ---------------------------------------------------------------------------
__global__ __launch_bounds__(128, 2) void gemm_tf32(
    const float* __restrict__ A, const float* __restrict__ Bm,
    float* __restrict__ C, int M, int N, int K)
{
    __shared__ float As[2][128][20];
    __shared__ float Bs[2][128][20];

    const int tid  = threadIdx.x;
    const int lane = tid & 31;
    const int warp = tid >> 5;
    const int wm   = (warp >> 1) * 64;
    const int wn   = (warp & 1) * 64;
    const int bm   = blockIdx.y * 128;
    const int bn   = blockIdx.x * 128;
    const int qr   = lane >> 2;
    const int qc   = lane & 3;

    float acc[4][8][4];
#pragma unroll
    for (int mt = 0; mt < 4; mt++)
#pragma unroll
        for (int nt = 0; nt < 8; nt++)
#pragma unroll
            for (int i = 0; i < 4; i++) acc[mt][nt][i] = 0.0f;

    const float* Abase = A  + (size_t)bm * K;
    const float* Bbase = Bm + (size_t)bn * K;

    auto stage = [&](int buf, int kb) {
        const float* Ab = Abase + kb * 16;
        const float* Bb = Bbase + kb * 16;
#pragma unroll
        for (int u = 0; u < 4; u++) {
            const int id = tid + u * 128;      // float4 id 0..511
            const int r  = id >> 2;
            const int c4 = (id & 3) * 4;
            cp_async16(&As[buf][r][c4], Ab + (size_t)r * K + c4);
            cp_async16(&Bs[buf][r][c4], Bb + (size_t)r * K + c4);
        }
    };

    const int nkb = K / 16;
    stage(0, 0);
    cp_commit();

    for (int kb = 0; kb < nkb; kb++) {
        __syncthreads();
        if (kb + 1 < nkb) stage((kb + 1) & 1, kb + 1);
        cp_commit();
        cp_wait<1>();
        __syncthreads();

        const int buf = kb & 1;
#pragma unroll
        for (int kk = 0; kk < 2; kk++) {
            const int k0 = kk * 8 + qc;
            uint32_t af[4][4], bf[8][2];
#pragma unroll
            for (int mt = 0; mt < 4; mt++) {
                const int m = wm + mt * 16 + qr;
                af[mt][0] = f2tf(As[buf][m][k0]);
                af[mt][1] = f2tf(As[buf][m + 8][k0]);
                af[mt][2] = f2tf(As[buf][m][k0 + 4]);
                af[mt][3] = f2tf(As[buf][m + 8][k0 + 4]);
            }
#pragma unroll
            for (int nt = 0; nt < 8; nt++) {
                const int n = wn + nt * 8 + qr;
                bf[nt][0] = f2tf(Bs[buf][n][k0]);
                bf[nt][1] = f2tf(Bs[buf][n][k0 + 4]);
            }
#pragma unroll
            for (int mt = 0; mt < 4; mt++)
#pragma unroll
                for (int nt = 0; nt < 8; nt++)
                    mma_tf32(acc[mt][nt], af[mt], bf[nt][0], bf[nt][1]);
        }
    }

#pragma unroll
    for (int mt = 0; mt < 4; mt++) {
        const int m = bm + wm + mt * 16 + qr;
#pragma unroll
        for (int nt = 0; nt < 8; nt++) {
            const int n = bn + wn + nt * 8 + qc * 2;
            *(float2*)&C[(size_t)m * N + n] =
                make_float2(acc[mt][nt][0], acc[mt][nt][1]);
            *(float2*)&C[(size_t)(m + 8) * N + n] =
                make_float2(acc[mt][nt][2], acc[mt][nt][3]);
        }
    }
}

// ---------------------------------------------------------------------------
// RoPE in-place on Q and the K half of KV
// ---------------------------------------------------------------------------
__global__ void rope_kernel(float* __restrict__ q, float* __restrict__ kv)
{
    const int NQ = TOK_ * NH_  * 32;
    const int NK = TOK_ * NKV_ * 32;
    const int i = blockIdx.x * blockDim.x + threadIdx.x;
    if (i >= NQ + NK) return;

    float* base;
    int t, p;
    if (i < NQ) {
        t = i / (NH_ * 32);
        const int r = i % (NH_ * 32);
        const int h = r / 32;
        p = r & 31;
        base = q + (size_t)t * H_ + h * HD_;
    } else {
        const int j = i - NQ;
        t = j / (NKV_ * 32);
        const int r = j % (NKV_ * 32);
        const int h = r / 32;
        p = r & 31;
        base = kv + (size_t)t * KVW_ + h * HD_;
    }
    const int s = t & (S_ - 1);
    const float inv = exp2f(-(float)p * 0.41524101186092029f);
    const float ang = (float)s * inv;
    float sn, c;
    __sincosf(ang, &sn, &c);
    const float x0 = base[p], x1 = base[p + 32];
    base[p]      = x0 * c - x1 * sn;
    base[p + 32] = x1 * c + x0 * sn;
}

// ---------------------------------------------------------------------------
// Causal flash attention, tf32 MMA, 128-query block, 4 warps, 32 rows/warp.
// R6: K and V staged in FRAGMENT-MAJOR smem layout (per k-octet, per lane,
// 16 b-frag words contiguous at stride-20-word lanes -> 4x LDS.128 per octet,
// conflict-free). PV uses the key-permutation trick (V row = 8*kk2 + 2qc + j)
// so the S C-fragment is directly the PV A-fragment.
//   KB: 8 octets * 640 words  = 5120 words (20480 B)
//   VB: same                    5120 words (20480 B)   total 40960 B static.
// ---------------------------------------------------------------------------
__global__ __launch_bounds__(128, 2) void flash_mma(
    const float* __restrict__ Q, const float* __restrict__ KV,
    float* __restrict__ O)
{
    __shared__ uint32_t SB[10240];
    uint32_t* KB = SB;
    uint32_t* VB = SB + 5120;

    const int tid  = threadIdx.x;
    const int lane = tid & 31;
    const int warp = tid >> 5;
    const int qr   = lane >> 2;
    const int qc   = lane & 3;
    const int bh   = blockIdx.y;
    const int b    = bh / NH_;
    const int h    = bh % NH_;
    const int g    = h / GRP_;
    const int m0   = ((int)gridDim.x - 1 - (int)blockIdx.x) * 128;  // heavy first
    const int wrow = warp * 32;

    // ---- stage Q (scaled by log2e/8) into plain-layout temp over KB/VB ----
    uint32_t (*Ktmp)[68] = (uint32_t(*)[68])KB;   // q rows 0..63
    uint32_t (*Vtmp)[68] = (uint32_t(*)[68])VB;   // q rows 64..127
    const float qs = 0.125f * 1.44269504088896341f;
    for (int i = tid; i < 128 * 16; i += 128) {
        const int r  = i >> 4;
        const int d4 = (i & 15) * 4;
        const float* qp = Q + (size_t)(b * S_ + m0 + r) * H_ + h * HD_ + d4;
        float4 v = *(const float4*)qp;
        uint32_t* dst = (r < 64) ? &Ktmp[r][d4] : &Vtmp[r - 64][d4];
        *(uint4*)dst = make_uint4(f2tf(v.x * qs), f2tf(v.y * qs),
                                  f2tf(v.z * qs), f2tf(v.w * qs));
    }
    __syncthreads();

    uint32_t qf[2][8][4];
#pragma unroll
    for (int mt = 0; mt < 2; mt++) {
        const int rbase = wrow + mt * 16;
#pragma unroll
        for (int kk = 0; kk < 8; kk++) {
            const int k = kk * 8 + qc;
            if (rbase < 64) {
                qf[mt][kk][0] = Ktmp[rbase + qr][k];
                qf[mt][kk][1] = Ktmp[rbase + qr + 8][k];
                qf[mt][kk][2] = Ktmp[rbase + qr][k + 4];
                qf[mt][kk][3] = Ktmp[rbase + qr + 8][k + 4];
            } else {
                qf[mt][kk][0] = Vtmp[rbase - 64 + qr][k];
                qf[mt][kk][1] = Vtmp[rbase - 64 + qr + 8][k];
                qf[mt][kk][2] = Vtmp[rbase - 64 + qr][k + 4];
                qf[mt][kk][3] = Vtmp[rbase - 64 + qr + 8][k + 4];
            }
        }
    }

    float of[2][8][4];
#pragma unroll
    for (int mt = 0; mt < 2; mt++)
#pragma unroll
        for (int dt = 0; dt < 8; dt++)
#pragma unroll
            for (int i = 0; i < 4; i++) of[mt][dt][i] = 0.0f;
    float m_run[2][2] = {{-1e30f, -1e30f}, {-1e30f, -1e30f}};
    float l_run[2][2] = {{0.0f, 0.0f}, {0.0f, 0.0f}};

    const size_t kvbase = (size_t)b * S_ * KVW_ + g * HD_;
    const int ntiles = m0 / 64 + 2;

    for (int kt = 0; kt < ntiles; kt++) {
        const int k0 = kt * 64;
        __syncthreads();
        // ---- stage K/V into fragment-major layout ----
        for (int i = tid; i < 64 * 16; i += 128) {
            const int r  = i >> 4;            // key 0..63
            const int d4 = (i & 15) * 4;      // d 0..60
            const float* kp = KV + kvbase + (size_t)(k0 + r) * KVW_ + d4;
            float4 k4 = *(const float4*)kp;
            float4 v4 = *(const float4*)(kp + 128);

            // K word (r, d4+t): kk=d4>>3, qc'=t, j=(d4>>2)&1, nt=r>>3, qr'=r&7
            {
                uint32_t* kb = KB + (d4 >> 3) * 640 + ((r & 7) * 4) * 20
                             + (r >> 3) * 2 + ((d4 >> 2) & 1);
                kb[0]  = f2tf(k4.x);
                kb[20] = f2tf(k4.y);
                kb[40] = f2tf(k4.z);
                kb[60] = f2tf(k4.w);
            }
            // V word (r, d4+t): kk2=r>>3, qc'=(r&7)>>1, j=r&1,
            //                   dt=(d4+t)>>3 (=d4>>3), qr'=(d4&7)+t
            {
                uint32_t* vb = VB + (r >> 3) * 640
                             + (((d4 & 7) * 4) + ((r & 7) >> 1)) * 20
                             + (d4 >> 3) * 2 + (r & 1);
                vb[0]  = f2tf(v4.x);
                vb[80] = f2tf(v4.y);    // +1 in qr' => +4*20 words
                vb[160] = f2tf(v4.z);
                vb[240] = f2tf(v4.w);
            }
        }
        __syncthreads();

        if (k0 > m0 + wrow + 31) continue;   // warp fully above the diagonal

        // ---- S = Q K^T (32 x 64 per warp); b-frags via LDS.128 ----
        float sf[2][8][4];
#pragma unroll
        for (int mt = 0; mt < 2; mt++)
#pragma unroll
            for (int nt = 0; nt < 8; nt++)
#pragma unroll
                for (int i = 0; i < 4; i++) sf[mt][nt][i] = 0.0f;

#pragma unroll
        for (int kk = 0; kk < 8; kk++) {
            const uint32_t* kp = KB + kk * 640 + lane * 20;
            uint4 b0 = *(const uint4*)(kp);
            uint4 b1 = *(const uint4*)(kp + 4);
            uint4 b2 = *(const uint4*)(kp + 8);
            uint4 b3 = *(const uint4*)(kp + 12);
#pragma unroll
            for (int mt = 0; mt < 2; mt++) {
                mma_tf32(sf[mt][0], qf[mt][kk], b0.x, b0.y);
                mma_tf32(sf[mt][1], qf[mt][kk], b0.z, b0.w);
                mma_tf32(sf[mt][2], qf[mt][kk], b1.x, b1.y);
                mma_tf32(sf[mt][3], qf[mt][kk], b1.z, b1.w);
                mma_tf32(sf[mt][4], qf[mt][kk], b2.x, b2.y);
                mma_tf32(sf[mt][5], qf[mt][kk], b2.z, b2.w);
                mma_tf32(sf[mt][6], qf[mt][kk], b3.x, b3.y);
                mma_tf32(sf[mt][7], qf[mt][kk], b3.z, b3.w);
            }
        }

        // ---- causal mask (diagonal region only) ----
        if (k0 + 63 > m0 + wrow) {
#pragma unroll
            for (int mt = 0; mt < 2; mt++) {
                const int r0 = m0 + wrow + mt * 16 + qr;
#pragma unroll
                for (int nt = 0; nt < 8; nt++) {
                    const int cL = k0 + nt * 8 + qc * 2;
                    if (cL     > r0)     sf[mt][nt][0] = -1e30f;
                    if (cL + 1 > r0)     sf[mt][nt][1] = -1e30f;
                    if (cL     > r0 + 8) sf[mt][nt][2] = -1e30f;
                    if (cL + 1 > r0 + 8) sf[mt][nt][3] = -1e30f;
                }
            }
        }

        // ---- online softmax (exp2 domain); tf32 P bits stored in place ----
#pragma unroll
        for (int mt = 0; mt < 2; mt++) {
            float tm0 = -1e30f, tm1 = -1e30f;
#pragma unroll
            for (int nt = 0; nt < 8; nt++) {
                tm0 = fmaxf(tm0, fmaxf(sf[mt][nt][0], sf[mt][nt][1]));
                tm1 = fmaxf(tm1, fmaxf(sf[mt][nt][2], sf[mt][nt][3]));
            }
            tm0 = fmaxf(tm0, __shfl_xor_sync(0xffffffffu, tm0, 1));
            tm0 = fmaxf(tm0, __shfl_xor_sync(0xffffffffu, tm0, 2));
            tm1 = fmaxf(tm1, __shfl_xor_sync(0xffffffffu, tm1, 1));
            tm1 = fmaxf(tm1, __shfl_xor_sync(0xffffffffu, tm1, 2));

            const float mn0 = fmaxf(m_run[mt][0], tm0);
            const float mn1 = fmaxf(m_run[mt][1], tm1);
            const float cor0 = exp2f(m_run[mt][0] - mn0);
            const float cor1 = exp2f(m_run[mt][1] - mn1);
            m_run[mt][0] = mn0; m_run[mt][1] = mn1;

            float rs0 = 0.0f, rs1 = 0.0f;
#pragma unroll
            for (int nt = 0; nt < 8; nt++) {
                const float p0 = exp2f(sf[mt][nt][0] - mn0);
                const float p1 = exp2f(sf[mt][nt][1] - mn0);
                const float p2 = exp2f(sf[mt][nt][2] - mn1);
                const float p3 = exp2f(sf[mt][nt][3] - mn1);
                rs0 += p0 + p1;
                rs1 += p2 + p3;
                sf[mt][nt][0] = __uint_as_float(f2tf(p0));
                sf[mt][nt][1] = __uint_as_float(f2tf(p1));
                sf[mt][nt][2] = __uint_as_float(f2tf(p2));
                sf[mt][nt][3] = __uint_as_float(f2tf(p3));
            }
            rs0 += __shfl_xor_sync(0xffffffffu, rs0, 1);
            rs0 += __shfl_xor_sync(0xffffffffu, rs0, 2);
            rs1 += __shfl_xor_sync(0xffffffffu, rs1, 1);
            rs1 += __shfl_xor_sync(0xffffffffu, rs1, 2);
            l_run[mt][0] = l_run[mt][0] * cor0 + rs0;
            l_run[mt][1] = l_run[mt][1] * cor1 + rs1;
#pragma unroll
            for (int dt = 0; dt < 8; dt++) {
                of[mt][dt][0] *= cor0; of[mt][dt][1] *= cor0;
                of[mt][dt][2] *= cor1; of[mt][dt][3] *= cor1;
            }
        }

        // ---- O += P V (S C-frag IS the PV A-frag; permuted-key V layout) ----
#pragma unroll
        for (int kk2 = 0; kk2 < 8; kk2++) {
            uint32_t af[2][4];
#pragma unroll
            for (int mt = 0; mt < 2; mt++) {
                af[mt][0] = __float_as_uint(sf[mt][kk2][0]);
                af[mt][1] = __float_as_uint(sf[mt][kk2][2]);
                af[mt][2] = __float_as_uint(sf[mt][kk2][1]);
                af[mt][3] = __float_as_uint(sf[mt][kk2][3]);
            }
            const uint32_t* vp = VB + kk2 * 640 + lane * 20;
            uint4 v0 = *(const uint4*)(vp);
            uint4 v1 = *(const uint4*)(vp + 4);
            uint4 v2 = *(const uint4*)(vp + 8);
            uint4 v3 = *(const uint4*)(vp + 12);
#pragma unroll
            for (int mt = 0; mt < 2; mt++) {
                mma_tf32(of[mt][0], af[mt], v0.x, v0.y);
                mma_tf32(of[mt][1], af[mt], v0.z, v0.w);
                mma_tf32(of[mt][2], af[mt], v1.x, v1.y);
                mma_tf32(of[mt][3], af[mt], v1.z, v1.w);
                mma_tf32(of[mt][4], af[mt], v2.x, v2.y);
                mma_tf32(of[mt][5], af[mt], v2.z, v2.w);
                mma_tf32(of[mt][6], af[mt], v3.x, v3.y);
                mma_tf32(of[mt][7], af[mt], v3.z, v3.w);
            }
        }
    }

    // ---- epilogue ----
#pragma unroll
    for (int mt = 0; mt < 2; mt++) {
        const float inv0 = 1.0f / l_run[mt][0];
        const float inv1 = 1.0f / l_run[mt][1];
        const int r0 = m0 + wrow + mt * 16 + qr;
#pragma unroll
        for (int dt = 0; dt < 8; dt++) {
            const int col = h * HD_ + dt * 8 + qc * 2;
            float* o0 = O + (size_t)(b * S_ + r0) * H_ + col;
            float* o1 = O + (size_t)(b * S_ + r0 + 8) * H_ + col;
            *(float2*)o0 = make_float2(of[mt][dt][0] * inv0, of[mt][dt][1] * inv0);
            *(float2*)o1 = make_float2(of[mt][dt][2] * inv1, of[mt][dt][3] * inv1);
        }
    }
}

// ---------------------------------------------------------------------------
// Launch
// ---------------------------------------------------------------------------
extern "C" void kernel_launch(void* const* d_in, const int* in_sizes, int n_in,
                              void* d_out, int out_size)
{
    const float* x   = (const float*)d_in[0];
    const float* wq  = (const float*)d_in[1];
    const float* wkv = (const float*)d_in[2];
    const float* wo  = (const float*)d_in[3];
    float* out = (float*)d_out;

    float *q, *kv, *att;
    cudaGetSymbolAddress((void**)&q,   g_q);
    cudaGetSymbolAddress((void**)&kv,  g_kv);
    cudaGetSymbolAddress((void**)&att, g_att);

    gemm_tf32<<<dim3(H_ / 128, TOK_ / 128), 128>>>(x, wq, q, TOK_, H_, H_);
    gemm_tf32<<<dim3(KVW_ / 128, TOK_ / 128), 128>>>(x, wkv, kv, TOK_, KVW_, H_);

    const int nrope = TOK_ * (NH_ + NKV_) * 32;
    rope_kernel<<<(nrope + 255) / 256, 256>>>(q, kv);

    flash_mma<<<dim3(S_ / 128, B_ * NH_), 128>>>(q, kv, att);

    gemm_tf32<<<dim3(H_ / 128, TOK_ / 128), 128>>>(att, wo, out, TOK_, H_, H_);
}

// round 8
// speedup vs baseline: 1.2000x; 1.0779x over previous
#include <cuda_runtime.h>
#include <cstdint>

// ---------------------------------------------------------------------------
// Problem constants
// ---------------------------------------------------------------------------
namespace {
constexpr int B_   = 4;
constexpr int S_   = 2048;
constexpr int H_   = 768;
constexpr int NH_  = 12;
constexpr int NKV_ = 2;
constexpr int HD_  = 64;
constexpr int GRP_ = NH_ / NKV_;      // 6
constexpr int TOK_ = B_ * S_;         // 8192
constexpr int KVW_ = 2 * NKV_ * HD_;  // 256
}

// ---------------------------------------------------------------------------
// Scratch (static device globals; no allocations allowed)
// ---------------------------------------------------------------------------
__device__ float g_q  [TOK_ * H_];    // [TOK, 768]
__device__ float g_kv [TOK_ * KVW_];  // [TOK, 256]  (K | V per kv-head)
__device__ float g_att[TOK_ * H_];    // [TOK, 768]

// ---------------------------------------------------------------------------
// helpers
// ---------------------------------------------------------------------------
__device__ __forceinline__ uint32_t f2tf(float x) {
    uint32_t r;
    asm("cvt.rna.tf32.f32 %0, %1;" : "=r"(r) : "f"(x));
    return r;
}

__device__ __forceinline__ void mma_tf32(float c[4], const uint32_t a[4],
                                         uint32_t b0, uint32_t b1) {
    asm volatile(
        "mma.sync.aligned.m16n8k8.row.col.f32.tf32.tf32.f32 "
        "{%0,%1,%2,%3}, {%4,%5,%6,%7}, {%8,%9}, {%0,%1,%2,%3};\n"
        : "+f"(c[0]), "+f"(c[1]), "+f"(c[2]), "+f"(c[3])
        : "r"(a[0]), "r"(a[1]), "r"(a[2]), "r"(a[3]), "r"(b0), "r"(b1));
}

__device__ __forceinline__ void cp_async16(void* smem_dst, const void* gmem_src) {
    uint32_t sa = (uint32_t)__cvta_generic_to_shared(smem_dst);
    asm volatile("cp.async.ca.shared.global [%0], [%1], 16;\n"
                 :: "r"(sa), "l"(gmem_src));
}
__device__ __forceinline__ void cp_commit() {
    asm volatile("cp.async.commit_group;\n");
}
template <int N>
__device__ __forceinline__ void cp_wait() {
    asm volatile("cp.async.wait_group %0;\n" :: "n"(N));
}

// ---------------------------------------------------------------------------
// tf32 GEMM: C[M,N] = A[M,K] * B[N,K]^T (row-major, K contiguous).
// 128x128 tile, BK=16, 128 threads / 4 warps, warp tile 64x64.
// ---------------------------------------------------------------------------
__global__ __launch_bounds__(128, 2) void gemm_tf32(
    const float* __restrict__ A, const float* __restrict__ Bm,
    float* __restrict__ C, int M, int N, int K)
{
    __shared__ float As[2][128][20];
    __shared__ float Bs[2][128][20];

    const int tid  = threadIdx.x;
    const int lane = tid & 31;
    const int warp = tid >> 5;
    const int wm   = (warp >> 1) * 64;
    const int wn   = (warp & 1) * 64;
    const int bm   = blockIdx.y * 128;
    const int bn   = blockIdx.x * 128;
    const int qr   = lane >> 2;
    const int qc   = lane & 3;

    float acc[4][8][4];
#pragma unroll
    for (int mt = 0; mt < 4; mt++)
#pragma unroll
        for (int nt = 0; nt < 8; nt++)
#pragma unroll
            for (int i = 0; i < 4; i++) acc[mt][nt][i] = 0.0f;

    const float* Abase = A  + (size_t)bm * K;
    const float* Bbase = Bm + (size_t)bn * K;

    auto stage = [&](int buf, int kb) {
        const float* Ab = Abase + kb * 16;
        const float* Bb = Bbase + kb * 16;
#pragma unroll
        for (int u = 0; u < 4; u++) {
            const int id = tid + u * 128;      // float4 id 0..511
            const int r  = id >> 2;
            const int c4 = (id & 3) * 4;
            cp_async16(&As[buf][r][c4], Ab + (size_t)r * K + c4);
            cp_async16(&Bs[buf][r][c4], Bb + (size_t)r * K + c4);
        }
    };

    const int nkb = K / 16;
    stage(0, 0);
    cp_commit();

    for (int kb = 0; kb < nkb; kb++) {
        __syncthreads();
        if (kb + 1 < nkb) stage((kb + 1) & 1, kb + 1);
        cp_commit();
        cp_wait<1>();
        __syncthreads();

        const int buf = kb & 1;
#pragma unroll
        for (int kk = 0; kk < 2; kk++) {
            const int k0 = kk * 8 + qc;
            uint32_t af[4][4], bf[8][2];
#pragma unroll
            for (int mt = 0; mt < 4; mt++) {
                const int m = wm + mt * 16 + qr;
                af[mt][0] = f2tf(As[buf][m][k0]);
                af[mt][1] = f2tf(As[buf][m + 8][k0]);
                af[mt][2] = f2tf(As[buf][m][k0 + 4]);
                af[mt][3] = f2tf(As[buf][m + 8][k0 + 4]);
            }
#pragma unroll
            for (int nt = 0; nt < 8; nt++) {
                const int n = wn + nt * 8 + qr;
                bf[nt][0] = f2tf(Bs[buf][n][k0]);
                bf[nt][1] = f2tf(Bs[buf][n][k0 + 4]);
            }
#pragma unroll
            for (int mt = 0; mt < 4; mt++)
#pragma unroll
                for (int nt = 0; nt < 8; nt++)
                    mma_tf32(acc[mt][nt], af[mt], bf[nt][0], bf[nt][1]);
        }
    }

#pragma unroll
    for (int mt = 0; mt < 4; mt++) {
        const int m = bm + wm + mt * 16 + qr;
#pragma unroll
        for (int nt = 0; nt < 8; nt++) {
            const int n = bn + wn + nt * 8 + qc * 2;
            *(float2*)&C[(size_t)m * N + n] =
                make_float2(acc[mt][nt][0], acc[mt][nt][1]);
            *(float2*)&C[(size_t)(m + 8) * N + n] =
                make_float2(acc[mt][nt][2], acc[mt][nt][3]);
        }
    }
}

// ---------------------------------------------------------------------------
// RoPE in-place on Q and the K half of KV
// ---------------------------------------------------------------------------
__global__ void rope_kernel(float* __restrict__ q, float* __restrict__ kv)
{
    const int NQ = TOK_ * NH_  * 32;
    const int NK = TOK_ * NKV_ * 32;
    const int i = blockIdx.x * blockDim.x + threadIdx.x;
    if (i >= NQ + NK) return;

    float* base;
    int t, p;
    if (i < NQ) {
        t = i / (NH_ * 32);
        const int r = i % (NH_ * 32);
        const int h = r / 32;
        p = r & 31;
        base = q + (size_t)t * H_ + h * HD_;
    } else {
        const int j = i - NQ;
        t = j / (NKV_ * 32);
        const int r = j % (NKV_ * 32);
        const int h = r / 32;
        p = r & 31;
        base = kv + (size_t)t * KVW_ + h * HD_;
    }
    const int s = t & (S_ - 1);
    const float inv = exp2f(-(float)p * 0.41524101186092029f);
    const float ang = (float)s * inv;
    float sn, c;
    __sincosf(ang, &sn, &c);
    const float x0 = base[p], x1 = base[p + 32];
    base[p]      = x0 * c - x1 * sn;
    base[p + 32] = x1 * c + x0 * sn;
}

// ---------------------------------------------------------------------------
// Causal flash attention, tf32 MMA, 128-query block, 4 warps, 32 rows/warp.
// R8 (= R7 resubmit): R4 compute + cp.async double-buffered K/V staging.
//   - K/V fetched raw one tile ahead (gmem latency overlapped with mma).
//   - K converted in-place to tf32 (RNA) after arrival; V left raw f32
//     (mma truncates; measured +1e-4 rel_err).
//   - PV key-permutation: S C-frag == PV A-frag (a = {c0,c2,c1,c3},
//     V rows 8*kk2 + 2qc + j).
// Dynamic smem: 2 buffers x (Ks 64x68 + Vs 64x68) u32 = 69632 B.
// ---------------------------------------------------------------------------
constexpr int FL_SMEM = 2 * (64 * 68 + 64 * 68) * 4;   // 69632

__global__ __launch_bounds__(128, 2) void flash_mma(
    const float* __restrict__ Q, const float* __restrict__ KV,
    float* __restrict__ O)
{
    extern __shared__ uint32_t SB[];   // [2][8704]: Ks (4352) | Vs (4352)

    const int tid  = threadIdx.x;
    const int lane = tid & 31;
    const int warp = tid >> 5;
    const int qr   = lane >> 2;
    const int qc   = lane & 3;
    const int bh   = blockIdx.y;
    const int b    = bh / NH_;
    const int h    = bh % NH_;
    const int g    = h / GRP_;
    const int m0   = ((int)gridDim.x - 1 - (int)blockIdx.x) * 128;  // heavy first
    const int wrow = warp * 32;

    // ---- stage Q (scaled by log2e/8, RNA tf32) through buffer 0 ----
    uint32_t (*Ktmp)[68] = (uint32_t(*)[68])SB;          // q rows 0..63
    uint32_t (*Vtmp)[68] = (uint32_t(*)[68])(SB + 4352); // q rows 64..127
    const float qs = 0.125f * 1.44269504088896341f;
    for (int i = tid; i < 128 * 16; i += 128) {
        const int r  = i >> 4;
        const int d4 = (i & 15) * 4;
        const float* qp = Q + (size_t)(b * S_ + m0 + r) * H_ + h * HD_ + d4;
        float4 v = *(const float4*)qp;
        uint32_t* dst = (r < 64) ? &Ktmp[r][d4] : &Vtmp[r - 64][d4];
        *(uint4*)dst = make_uint4(f2tf(v.x * qs), f2tf(v.y * qs),
                                  f2tf(v.z * qs), f2tf(v.w * qs));
    }
    __syncthreads();

    uint32_t qf[2][8][4];
#pragma unroll
    for (int mt = 0; mt < 2; mt++) {
        const int rbase = wrow + mt * 16;
#pragma unroll
        for (int kk = 0; kk < 8; kk++) {
            const int k = kk * 8 + qc;
            if (rbase < 64) {
                qf[mt][kk][0] = Ktmp[rbase + qr][k];
                qf[mt][kk][1] = Ktmp[rbase + qr + 8][k];
                qf[mt][kk][2] = Ktmp[rbase + qr][k + 4];
                qf[mt][kk][3] = Ktmp[rbase + qr + 8][k + 4];
            } else {
                qf[mt][kk][0] = Vtmp[rbase - 64 + qr][k];
                qf[mt][kk][1] = Vtmp[rbase - 64 + qr + 8][k];
                qf[mt][kk][2] = Vtmp[rbase - 64 + qr][k + 4];
                qf[mt][kk][3] = Vtmp[rbase - 64 + qr + 8][k + 4];
            }
        }
    }
    __syncthreads();   // Q region free for cp.async staging

    float of[2][8][4];
#pragma unroll
    for (int mt = 0; mt < 2; mt++)
#pragma unroll
        for (int dt = 0; dt < 8; dt++)
#pragma unroll
            for (int i = 0; i < 4; i++) of[mt][dt][i] = 0.0f;
    float m_run[2][2] = {{-1e30f, -1e30f}, {-1e30f, -1e30f}};
    float l_run[2][2] = {{0.0f, 0.0f}, {0.0f, 0.0f}};

    const size_t kvbase = (size_t)b * S_ * KVW_ + g * HD_;
    const int ntiles = m0 / 64 + 2;

    // ---- raw cp.async stage of one 64-key K/V tile into buffer `buf` ----
    auto stage = [&](int kt, int buf) {
        uint32_t* Kb = SB + buf * 8704;
        uint32_t* Vb = Kb + 4352;
        const float* base = KV + kvbase + (size_t)(kt * 64) * KVW_;
#pragma unroll
        for (int u = 0; u < 8; u++) {
            const int i  = tid + u * 128;      // float4 id 0..1023
            const int r  = i >> 4;
            const int c4 = (i & 15) * 4;
            const float* kp = base + (size_t)r * KVW_ + c4;
            cp_async16(Kb + r * 68 + c4, kp);
            cp_async16(Vb + r * 68 + c4, kp + 128);
        }
    };

    stage(0, 0);
    cp_commit();

    for (int kt = 0; kt < ntiles; kt++) {
        const int buf = kt & 1;
        if (kt + 1 < ntiles) stage(kt + 1, buf ^ 1);
        cp_commit();                 // empty group OK on last iteration
        cp_wait<1>();                // tile kt's group complete
        __syncthreads();

        uint32_t* Kb = SB + buf * 8704;
        uint32_t (*Ks)[68] = (uint32_t(*)[68])Kb;
        uint32_t (*Vs)[68] = (uint32_t(*)[68])(Kb + 4352);

        // ---- convert K tile in place to tf32 (RNA); V stays raw ----
#pragma unroll
        for (int u = 0; u < 8; u++) {
            const int i = tid + u * 128;
            uint32_t* p = Kb + (i >> 4) * 68 + (i & 15) * 4;
            uint4 w = *(uint4*)p;
            w.x = f2tf(__uint_as_float(w.x));
            w.y = f2tf(__uint_as_float(w.y));
            w.z = f2tf(__uint_as_float(w.z));
            w.w = f2tf(__uint_as_float(w.w));
            *(uint4*)p = w;
        }
        __syncthreads();

        const int k0 = kt * 64;
        if (k0 <= m0 + wrow + 31) {     // warp has unmasked keys in this tile
            // ---- S = Q K^T (32 x 64 per warp), b-frags shared across mt ----
            float sf[2][8][4];
#pragma unroll
            for (int mt = 0; mt < 2; mt++)
#pragma unroll
                for (int nt = 0; nt < 8; nt++)
#pragma unroll
                    for (int i = 0; i < 4; i++) sf[mt][nt][i] = 0.0f;
#pragma unroll
            for (int kk = 0; kk < 8; kk++) {
#pragma unroll
                for (int nh = 0; nh < 2; nh++) {
                    uint32_t bfr[4][2];
#pragma unroll
                    for (int nt = 0; nt < 4; nt++) {
                        const int n = (nh * 4 + nt) * 8 + qr;
                        bfr[nt][0] = Ks[n][kk * 8 + qc];
                        bfr[nt][1] = Ks[n][kk * 8 + qc + 4];
                    }
#pragma unroll
                    for (int mt = 0; mt < 2; mt++)
#pragma unroll
                        for (int nt = 0; nt < 4; nt++)
                            mma_tf32(sf[mt][nh * 4 + nt], qf[mt][kk],
                                     bfr[nt][0], bfr[nt][1]);
                }
            }

            // ---- causal mask (diagonal region only) ----
            if (k0 + 63 > m0 + wrow) {
#pragma unroll
                for (int mt = 0; mt < 2; mt++) {
                    const int r0 = m0 + wrow + mt * 16 + qr;
#pragma unroll
                    for (int nt = 0; nt < 8; nt++) {
                        const int cL = k0 + nt * 8 + qc * 2;
                        if (cL     > r0)     sf[mt][nt][0] = -1e30f;
                        if (cL + 1 > r0)     sf[mt][nt][1] = -1e30f;
                        if (cL     > r0 + 8) sf[mt][nt][2] = -1e30f;
                        if (cL + 1 > r0 + 8) sf[mt][nt][3] = -1e30f;
                    }
                }
            }

            // ---- online softmax (exp2 domain); tf32 P bits in place ----
#pragma unroll
            for (int mt = 0; mt < 2; mt++) {
                float tm0 = -1e30f, tm1 = -1e30f;
#pragma unroll
                for (int nt = 0; nt < 8; nt++) {
                    tm0 = fmaxf(tm0, fmaxf(sf[mt][nt][0], sf[mt][nt][1]));
                    tm1 = fmaxf(tm1, fmaxf(sf[mt][nt][2], sf[mt][nt][3]));
                }
                tm0 = fmaxf(tm0, __shfl_xor_sync(0xffffffffu, tm0, 1));
                tm0 = fmaxf(tm0, __shfl_xor_sync(0xffffffffu, tm0, 2));
                tm1 = fmaxf(tm1, __shfl_xor_sync(0xffffffffu, tm1, 1));
                tm1 = fmaxf(tm1, __shfl_xor_sync(0xffffffffu, tm1, 2));

                const float mn0 = fmaxf(m_run[mt][0], tm0);
                const float mn1 = fmaxf(m_run[mt][1], tm1);
                const float cor0 = exp2f(m_run[mt][0] - mn0);
                const float cor1 = exp2f(m_run[mt][1] - mn1);
                m_run[mt][0] = mn0; m_run[mt][1] = mn1;

                float rs0 = 0.0f, rs1 = 0.0f;
#pragma unroll
                for (int nt = 0; nt < 8; nt++) {
                    const float p0 = exp2f(sf[mt][nt][0] - mn0);
                    const float p1 = exp2f(sf[mt][nt][1] - mn0);
                    const float p2 = exp2f(sf[mt][nt][2] - mn1);
                    const float p3 = exp2f(sf[mt][nt][3] - mn1);
                    rs0 += p0 + p1;
                    rs1 += p2 + p3;
                    sf[mt][nt][0] = __uint_as_float(f2tf(p0));
                    sf[mt][nt][1] = __uint_as_float(f2tf(p1));
                    sf[mt][nt][2] = __uint_as_float(f2tf(p2));
                    sf[mt][nt][3] = __uint_as_float(f2tf(p3));
                }
                rs0 += __shfl_xor_sync(0xffffffffu, rs0, 1);
                rs0 += __shfl_xor_sync(0xffffffffu, rs0, 2);
                rs1 += __shfl_xor_sync(0xffffffffu, rs1, 1);
                rs1 += __shfl_xor_sync(0xffffffffu, rs1, 2);
                l_run[mt][0] = l_run[mt][0] * cor0 + rs0;
                l_run[mt][1] = l_run[mt][1] * cor1 + rs1;
#pragma unroll
                for (int dt = 0; dt < 8; dt++) {
                    of[mt][dt][0] *= cor0; of[mt][dt][1] *= cor0;
                    of[mt][dt][2] *= cor1; of[mt][dt][3] *= cor1;
                }
            }

            // ---- O += P V (S C-frag IS PV A-frag; key-permuted V rows) ----
#pragma unroll
            for (int kk2 = 0; kk2 < 8; kk2++) {
                uint32_t af[2][4];
#pragma unroll
                for (int mt = 0; mt < 2; mt++) {
                    af[mt][0] = __float_as_uint(sf[mt][kk2][0]);
                    af[mt][1] = __float_as_uint(sf[mt][kk2][2]);
                    af[mt][2] = __float_as_uint(sf[mt][kk2][1]);
                    af[mt][3] = __float_as_uint(sf[mt][kk2][3]);
                }
                const int vrow = kk2 * 8 + 2 * qc;
#pragma unroll
                for (int dh = 0; dh < 2; dh++) {
                    uint32_t vb[4][2];
#pragma unroll
                    for (int dt = 0; dt < 4; dt++) {
                        const int d = (dh * 4 + dt) * 8 + qr;
                        vb[dt][0] = Vs[vrow][d];
                        vb[dt][1] = Vs[vrow + 1][d];
                    }
#pragma unroll
                    for (int mt = 0; mt < 2; mt++)
#pragma unroll
                        for (int dt = 0; dt < 4; dt++)
                            mma_tf32(of[mt][dh * 4 + dt], af[mt],
                                     vb[dt][0], vb[dt][1]);
                }
            }
        }
        __syncthreads();   // compute done: buffer reusable for kt+2 staging
    }

    // ---- epilogue ----
#pragma unroll
    for (int mt = 0; mt < 2; mt++) {
        const float inv0 = 1.0f / l_run[mt][0];
        const float inv1 = 1.0f / l_run[mt][1];
        const int r0 = m0 + wrow + mt * 16 + qr;
#pragma unroll
        for (int dt = 0; dt < 8; dt++) {
            const int col = h * HD_ + dt * 8 + qc * 2;
            float* o0 = O + (size_t)(b * S_ + r0) * H_ + col;
            float* o1 = O + (size_t)(b * S_ + r0 + 8) * H_ + col;
            *(float2*)o0 = make_float2(of[mt][dt][0] * inv0, of[mt][dt][1] * inv0);
            *(float2*)o1 = make_float2(of[mt][dt][2] * inv1, of[mt][dt][3] * inv1);
        }
    }
}

// ---------------------------------------------------------------------------
// Launch
// ---------------------------------------------------------------------------
extern "C" void kernel_launch(void* const* d_in, const int* in_sizes, int n_in,
                              void* d_out, int out_size)
{
    const float* x   = (const float*)d_in[0];
    const float* wq  = (const float*)d_in[1];
    const float* wkv = (const float*)d_in[2];
    const float* wo  = (const float*)d_in[3];
    float* out = (float*)d_out;

    float *q, *kv, *att;
    cudaGetSymbolAddress((void**)&q,   g_q);
    cudaGetSymbolAddress((void**)&kv,  g_kv);
    cudaGetSymbolAddress((void**)&att, g_att);

    cudaFuncSetAttribute(flash_mma,
                         cudaFuncAttributeMaxDynamicSharedMemorySize, FL_SMEM);

    gemm_tf32<<<dim3(H_ / 128, TOK_ / 128), 128>>>(x, wq, q, TOK_, H_, H_);
    gemm_tf32<<<dim3(KVW_ / 128, TOK_ / 128), 128>>>(x, wkv, kv, TOK_, KVW_, H_);

    const int nrope = TOK_ * (NH_ + NKV_) * 32;
    rope_kernel<<<(nrope + 255) / 256, 256>>>(q, kv);

    flash_mma<<<dim3(S_ / 128, B_ * NH_), 128, FL_SMEM>>>(q, kv, att);

    gemm_tf32<<<dim3(H_ / 128, TOK_ / 128), 128>>>(att, wo, out, TOK_, H_, H_);
}

// round 11
// speedup vs baseline: 1.7133x; 1.4277x over previous
#include <cuda_runtime.h>
#include <cuda_fp16.h>
#include <cstdint>

// ---------------------------------------------------------------------------
// Problem constants
// ---------------------------------------------------------------------------
namespace {
constexpr int B_   = 4;
constexpr int S_   = 2048;
constexpr int H_   = 768;
constexpr int NH_  = 12;
constexpr int NKV_ = 2;
constexpr int HD_  = 64;
constexpr int GRP_ = NH_ / NKV_;      // 6
constexpr int TOK_ = B_ * S_;         // 8192
constexpr int KVW_ = 2 * NKV_ * HD_;  // 256
}

// ---------------------------------------------------------------------------
// Scratch (static device globals; no allocations allowed)
// ---------------------------------------------------------------------------
__device__ float    g_q   [TOK_ * H_];        // fp32 Q (rope'd in place)
__device__ float    g_kv  [TOK_ * KVW_];      // fp32 KV (K rope'd in place)
__device__ uint32_t g_xh  [TOK_ * H_ / 2];    // half2-packed x
__device__ uint32_t g_wqh [H_ * H_ / 2];
__device__ uint32_t g_wkvh[KVW_ * H_ / 2];
__device__ uint32_t g_woh [H_ * H_ / 2];
__device__ uint32_t g_atth[TOK_ * H_ / 2];    // half2-packed attention output

// ---------------------------------------------------------------------------
// helpers
// ---------------------------------------------------------------------------
__device__ __forceinline__ uint32_t pack_half2(float lo, float hi) {
    uint32_t r;
    asm("cvt.rn.f16x2.f32 %0, %1, %2;" : "=r"(r) : "f"(hi), "f"(lo));
    return r;
}

__device__ __forceinline__ void mma_f16(float c[4], const uint32_t a[4],
                                        uint32_t b0, uint32_t b1) {
    asm volatile(
        "mma.sync.aligned.m16n8k16.row.col.f32.f16.f16.f32 "
        "{%0,%1,%2,%3}, {%4,%5,%6,%7}, {%8,%9}, {%0,%1,%2,%3};\n"
        : "+f"(c[0]), "+f"(c[1]), "+f"(c[2]), "+f"(c[3])
        : "r"(a[0]), "r"(a[1]), "r"(a[2]), "r"(a[3]), "r"(b0), "r"(b1));
}

__device__ __forceinline__ void cp_async16(void* smem_dst, const void* gmem_src) {
    uint32_t sa = (uint32_t)__cvta_generic_to_shared(smem_dst);
    asm volatile("cp.async.ca.shared.global [%0], [%1], 16;\n"
                 :: "r"(sa), "l"(gmem_src));
}
__device__ __forceinline__ void cp_commit() {
    asm volatile("cp.async.commit_group;\n");
}
template <int N>
__device__ __forceinline__ void cp_wait() {
    asm volatile("cp.async.wait_group %0;\n" :: "n"(N));
}

// ---------------------------------------------------------------------------
// fp32 -> packed half2 convert
// ---------------------------------------------------------------------------
__global__ void cvt_half(const float* __restrict__ src,
                         uint32_t* __restrict__ dst, int n4)
{
    const int i = blockIdx.x * 256 + threadIdx.x;
    if (i >= n4) return;
    float4 v = ((const float4*)src)[i];
    dst[i * 2]     = pack_half2(v.x, v.y);
    dst[i * 2 + 1] = pack_half2(v.z, v.w);
}

// ---------------------------------------------------------------------------
// fp16 GEMM: C[M,N](f32) = A[M,K](half) * B[N,K](half)^T.
// 128x128 tile, BK=16, 128 threads / 4 warps, warp tile 64x64,
// cp.async double-buffered. smem rows = 8 half2 words + 4 pad (stride 12:
// 12*qr+qc ≡ 4qr+qc mod 32 -> conflict-free fragment loads).
// ---------------------------------------------------------------------------
constexpr int GM_SMEM = 2 * 2 * 128 * 12 * 4;   // 49152 B

__global__ __launch_bounds__(128, 2) void gemm_fp16(
    const __half* __restrict__ A, const __half* __restrict__ B,
    float* __restrict__ C, int M, int N, int K)
{
    extern __shared__ uint32_t GS[];   // As[2][1536] | Bs[2][1536]

    const int tid  = threadIdx.x;
    const int lane = tid & 31;
    const int warp = tid >> 5;
    const int wm   = (warp >> 1) * 64;
    const int wn   = (warp & 1) * 64;
    const int bm   = blockIdx.y * 128;
    const int bn   = blockIdx.x * 128;
    const int qr   = lane >> 2;
    const int qc   = lane & 3;

    float acc[4][8][4];
#pragma unroll
    for (int mt = 0; mt < 4; mt++)
#pragma unroll
        for (int nt = 0; nt < 8; nt++)
#pragma unroll
            for (int i = 0; i < 4; i++) acc[mt][nt][i] = 0.0f;

    const __half* Abase = A + (size_t)bm * K;
    const __half* Bbase = B + (size_t)bn * K;

    auto stage = [&](int buf, int kb) {
        uint32_t* As = GS + buf * 1536;
        uint32_t* Bs = GS + 3072 + buf * 1536;
        const __half* Ab = Abase + kb * 16;
        const __half* Bb = Bbase + kb * 16;
#pragma unroll
        for (int u = 0; u < 2; u++) {
            const int id  = tid + u * 128;     // 0..255
            const int r   = id >> 1;
            const int seg = id & 1;
            cp_async16(As + r * 12 + seg * 4, Ab + (size_t)r * K + seg * 8);
            cp_async16(Bs + r * 12 + seg * 4, Bb + (size_t)r * K + seg * 8);
        }
    };

    const int nkb = K / 16;
    stage(0, 0);
    cp_commit();

    for (int kb = 0; kb < nkb; kb++) {
        __syncthreads();
        if (kb + 1 < nkb) stage((kb + 1) & 1, kb + 1);
        cp_commit();
        cp_wait<1>();
        __syncthreads();

        const uint32_t* As = GS + (kb & 1) * 1536;
        const uint32_t* Bs = GS + 3072 + (kb & 1) * 1536;

        uint32_t af[4][4], bf[8][2];
#pragma unroll
        for (int mt = 0; mt < 4; mt++) {
            const int m = wm + mt * 16 + qr;
            af[mt][0] = As[m * 12 + qc];
            af[mt][1] = As[(m + 8) * 12 + qc];
            af[mt][2] = As[m * 12 + qc + 4];
            af[mt][3] = As[(m + 8) * 12 + qc + 4];
        }
#pragma unroll
        for (int nt = 0; nt < 8; nt++) {
            const int n = wn + nt * 8 + qr;
            bf[nt][0] = Bs[n * 12 + qc];
            bf[nt][1] = Bs[n * 12 + qc + 4];
        }
#pragma unroll
        for (int mt = 0; mt < 4; mt++)
#pragma unroll
            for (int nt = 0; nt < 8; nt++)
                mma_f16(acc[mt][nt], af[mt], bf[nt][0], bf[nt][1]);
    }

#pragma unroll
    for (int mt = 0; mt < 4; mt++) {
        const int m = bm + wm + mt * 16 + qr;
#pragma unroll
        for (int nt = 0; nt < 8; nt++) {
            const int n = bn + wn + nt * 8 + qc * 2;
            *(float2*)&C[(size_t)m * N + n] =
                make_float2(acc[mt][nt][0], acc[mt][nt][1]);
            *(float2*)&C[(size_t)(m + 8) * N + n] =
                make_float2(acc[mt][nt][2], acc[mt][nt][3]);
        }
    }
}

// ---------------------------------------------------------------------------
// RoPE in-place on Q and the K half of KV (fp32)
// ---------------------------------------------------------------------------
__global__ void rope_kernel(float* __restrict__ q, float* __restrict__ kv)
{
    const int NQ = TOK_ * NH_  * 32;
    const int NK = TOK_ * NKV_ * 32;
    const int i = blockIdx.x * blockDim.x + threadIdx.x;
    if (i >= NQ + NK) return;

    float* base;
    int t, p;
    if (i < NQ) {
        t = i / (NH_ * 32);
        const int r = i % (NH_ * 32);
        const int h = r / 32;
        p = r & 31;
        base = q + (size_t)t * H_ + h * HD_;
    } else {
        const int j = i - NQ;
        t = j / (NKV_ * 32);
        const int r = j % (NKV_ * 32);
        const int h = r / 32;
        p = r & 31;
        base = kv + (size_t)t * KVW_ + h * HD_;
    }
    const int s = t & (S_ - 1);
    const float inv = exp2f(-(float)p * 0.41524101186092029f);
    const float ang = (float)s * inv;
    float sn, c;
    __sincosf(ang, &sn, &c);
    const float x0 = base[p], x1 = base[p + 32];
    base[p]      = x0 * c - x1 * sn;
    base[p + 32] = x1 * c + x0 * sn;
}

// ---------------------------------------------------------------------------
// Causal flash attention, fp16 m16n8k16 MMA, 128-query block, 4 warps,
// 32 rows/warp. R4 loop structure (best measured), half the mma count.
//   Ks[key][36 words]: d-pair half2, stride 36 -> 4qr+qc conflict-free.
//   Vs[d][36 words]:   key-pair half2 (d-major) -> PV B-frag natural.
//   P C-frag packs to PV A-frag as half2 of adjacent S columns (identity
//   key order -- no shuffle, no permutation).
// Output written as packed half2 into g_atth for the final GEMM.
// ---------------------------------------------------------------------------
__global__ __launch_bounds__(128, 2) void flash_f16(
    const float* __restrict__ Q, const float* __restrict__ KV,
    uint32_t* __restrict__ Oh)
{
    __shared__ uint32_t Ks[64 * 36];   // 9216 B
    __shared__ uint32_t Vs[64 * 36];   // 9216 B

    const int tid  = threadIdx.x;
    const int lane = tid & 31;
    const int warp = tid >> 5;
    const int qr   = lane >> 2;
    const int qc   = lane & 3;
    const int bh   = blockIdx.y;
    const int b    = bh / NH_;
    const int h    = bh % NH_;
    const int g    = h / GRP_;
    const int m0   = ((int)gridDim.x - 1 - (int)blockIdx.x) * 128;  // heavy first
    const int wrow = warp * 32;

    // ---- stage Q (scaled by log2e/8) as half2 d-pairs into Ks/Vs ----
    const float qs = 0.125f * 1.44269504088896341f;
    for (int i = tid; i < 128 * 16; i += 128) {
        const int r  = i >> 4;
        const int d4 = (i & 15) * 4;
        const float* qp = Q + (size_t)(b * S_ + m0 + r) * H_ + h * HD_ + d4;
        float4 v = *(const float4*)qp;
        uint32_t* dst = (r < 64) ? &Ks[r * 36 + d4 / 2]
                                 : &Vs[(r - 64) * 36 + d4 / 2];
        dst[0] = pack_half2(v.x * qs, v.y * qs);
        dst[1] = pack_half2(v.z * qs, v.w * qs);
    }
    __syncthreads();

    // qf[mt][kg] = A-frag for k-group kg (d = kg*16 .. kg*16+15)
    uint32_t qf[2][4][4];
#pragma unroll
    for (int mt = 0; mt < 2; mt++) {
        const int rbase = wrow + mt * 16;
        const uint32_t* Qa = (rbase < 64) ? &Ks[rbase * 36]
                                          : &Vs[(rbase - 64) * 36];
#pragma unroll
        for (int kg = 0; kg < 4; kg++) {
            const int c = kg * 8 + qc;
            qf[mt][kg][0] = Qa[qr * 36 + c];
            qf[mt][kg][1] = Qa[(qr + 8) * 36 + c];
            qf[mt][kg][2] = Qa[qr * 36 + c + 4];
            qf[mt][kg][3] = Qa[(qr + 8) * 36 + c + 4];
        }
    }

    float of[2][8][4];
#pragma unroll
    for (int mt = 0; mt < 2; mt++)
#pragma unroll
        for (int dt = 0; dt < 8; dt++)
#pragma unroll
            for (int i = 0; i < 4; i++) of[mt][dt][i] = 0.0f;
    float m_run[2][2] = {{-1e30f, -1e30f}, {-1e30f, -1e30f}};
    float l_run[2][2] = {{0.0f, 0.0f}, {0.0f, 0.0f}};

    const size_t kvbase = (size_t)b * S_ * KVW_ + g * HD_;
    const int ntiles = m0 / 64 + 2;

    for (int kt = 0; kt < ntiles; kt++) {
        const int k0 = kt * 64;
        __syncthreads();
        // K: word(key, dp) = half2(K[key][2dp], K[key][2dp+1])
#pragma unroll
        for (int u = 0; u < 8; u++) {
            const int i   = tid + u * 128;
            const int key = i >> 4;
            const int d4  = (i & 15) * 4;
            float4 k4 = *(const float4*)(KV + kvbase +
                                         (size_t)(k0 + key) * KVW_ + d4);
            Ks[key * 36 + d4 / 2]     = pack_half2(k4.x, k4.y);
            Ks[key * 36 + d4 / 2 + 1] = pack_half2(k4.z, k4.w);
        }
        // V: word(d, kp) = half2(V[2kp][d], V[2kp+1][d])  (d-major)
#pragma unroll
        for (int u = 0; u < 16; u++) {
            const int i  = tid + u * 128;
            const int d  = i & 63;
            const int kp = i >> 6;
            const float* vp = KV + kvbase +
                              (size_t)(k0 + 2 * kp) * KVW_ + 128 + d;
            Vs[d * 36 + kp] = pack_half2(vp[0], vp[KVW_]);
        }
        __syncthreads();

        if (k0 > m0 + wrow + 31) continue;   // warp fully above the diagonal

        // ---- S = Q K^T (32 x 64 per warp) ----
        float sf[2][8][4];
#pragma unroll
        for (int mt = 0; mt < 2; mt++)
#pragma unroll
            for (int nt = 0; nt < 8; nt++)
#pragma unroll
                for (int i = 0; i < 4; i++) sf[mt][nt][i] = 0.0f;
#pragma unroll
        for (int kg = 0; kg < 4; kg++) {
#pragma unroll
            for (int nh = 0; nh < 2; nh++) {
                uint32_t bfr[4][2];
#pragma unroll
                for (int nt = 0; nt < 4; nt++) {
                    const int n = (nh * 4 + nt) * 8 + qr;
                    bfr[nt][0] = Ks[n * 36 + kg * 8 + qc];
                    bfr[nt][1] = Ks[n * 36 + kg * 8 + qc + 4];
                }
#pragma unroll
                for (int mt = 0; mt < 2; mt++)
#pragma unroll
                    for (int nt = 0; nt < 4; nt++)
                        mma_f16(sf[mt][nh * 4 + nt], qf[mt][kg],
                                bfr[nt][0], bfr[nt][1]);
            }
        }

        // ---- causal mask (diagonal region only) ----
        if (k0 + 63 > m0 + wrow) {
#pragma unroll
            for (int mt = 0; mt < 2; mt++) {
                const int r0 = m0 + wrow + mt * 16 + qr;
#pragma unroll
                for (int nt = 0; nt < 8; nt++) {
                    const int cL = k0 + nt * 8 + qc * 2;
                    if (cL     > r0)     sf[mt][nt][0] = -1e30f;
                    if (cL + 1 > r0)     sf[mt][nt][1] = -1e30f;
                    if (cL     > r0 + 8) sf[mt][nt][2] = -1e30f;
                    if (cL + 1 > r0 + 8) sf[mt][nt][3] = -1e30f;
                }
            }
        }

        // ---- online softmax (exp2 domain); P packed to half2 ----
        uint32_t pp[2][8][2];
#pragma unroll
        for (int mt = 0; mt < 2; mt++) {
            float tm0 = -1e30f, tm1 = -1e30f;
#pragma unroll
            for (int nt = 0; nt < 8; nt++) {
                tm0 = fmaxf(tm0, fmaxf(sf[mt][nt][0], sf[mt][nt][1]));
                tm1 = fmaxf(tm1, fmaxf(sf[mt][nt][2], sf[mt][nt][3]));
            }
            tm0 = fmaxf(tm0, __shfl_xor_sync(0xffffffffu, tm0, 1));
            tm0 = fmaxf(tm0, __shfl_xor_sync(0xffffffffu, tm0, 2));
            tm1 = fmaxf(tm1, __shfl_xor_sync(0xffffffffu, tm1, 1));
            tm1 = fmaxf(tm1, __shfl_xor_sync(0xffffffffu, tm1, 2));

            const float mn0 = fmaxf(m_run[mt][0], tm0);
            const float mn1 = fmaxf(m_run[mt][1], tm1);
            const float cor0 = exp2f(m_run[mt][0] - mn0);
            const float cor1 = exp2f(m_run[mt][1] - mn1);
            m_run[mt][0] = mn0; m_run[mt][1] = mn1;

            float rs0 = 0.0f, rs1 = 0.0f;
#pragma unroll
            for (int nt = 0; nt < 8; nt++) {
                const float p0 = exp2f(sf[mt][nt][0] - mn0);
                const float p1 = exp2f(sf[mt][nt][1] - mn0);
                const float p2 = exp2f(sf[mt][nt][2] - mn1);
                const float p3 = exp2f(sf[mt][nt][3] - mn1);
                rs0 += p0 + p1;
                rs1 += p2 + p3;
                pp[mt][nt][0] = pack_half2(p0, p1);   // row qr,  adjacent keys
                pp[mt][nt][1] = pack_half2(p2, p3);   // row qr+8
            }
            rs0 += __shfl_xor_sync(0xffffffffu, rs0, 1);
            rs0 += __shfl_xor_sync(0xffffffffu, rs0, 2);
            rs1 += __shfl_xor_sync(0xffffffffu, rs1, 1);
            rs1 += __shfl_xor_sync(0xffffffffu, rs1, 2);
            l_run[mt][0] = l_run[mt][0] * cor0 + rs0;
            l_run[mt][1] = l_run[mt][1] * cor1 + rs1;
#pragma unroll
            for (int dt = 0; dt < 8; dt++) {
                of[mt][dt][0] *= cor0; of[mt][dt][1] *= cor0;
                of[mt][dt][2] *= cor1; of[mt][dt][3] *= cor1;
            }
        }

        // ---- O += P V  (A-frag = packed P, identity key order) ----
#pragma unroll
        for (int kg = 0; kg < 4; kg++) {
            uint32_t af[2][4];
#pragma unroll
            for (int mt = 0; mt < 2; mt++) {
                af[mt][0] = pp[mt][2 * kg][0];
                af[mt][1] = pp[mt][2 * kg][1];
                af[mt][2] = pp[mt][2 * kg + 1][0];
                af[mt][3] = pp[mt][2 * kg + 1][1];
            }
#pragma unroll
            for (int dh = 0; dh < 2; dh++) {
                uint32_t vb[4][2];
#pragma unroll
                for (int dt = 0; dt < 4; dt++) {
                    const int d = (dh * 4 + dt) * 8 + qr;
                    vb[dt][0] = Vs[d * 36 + kg * 8 + qc];
                    vb[dt][1] = Vs[d * 36 + kg * 8 + qc + 4];
                }
#pragma unroll
                for (int mt = 0; mt < 2; mt++)
#pragma unroll
                    for (int dt = 0; dt < 4; dt++)
                        mma_f16(of[mt][dh * 4 + dt], af[mt],
                                vb[dt][0], vb[dt][1]);
            }
        }
    }

    // ---- epilogue: write packed half2 att ----
#pragma unroll
    for (int mt = 0; mt < 2; mt++) {
        const float inv0 = 1.0f / l_run[mt][0];
        const float inv1 = 1.0f / l_run[mt][1];
        const int r0 = m0 + wrow + mt * 16 + qr;
#pragma unroll
        for (int dt = 0; dt < 8; dt++) {
            const int col = h * HD_ + dt * 8 + qc * 2;
            Oh[((size_t)(b * S_ + r0) * H_ + col) >> 1] =
                pack_half2(of[mt][dt][0] * inv0, of[mt][dt][1] * inv0);
            Oh[((size_t)(b * S_ + r0 + 8) * H_ + col) >> 1] =
                pack_half2(of[mt][dt][2] * inv1, of[mt][dt][3] * inv1);
        }
    }
}

// ---------------------------------------------------------------------------
// Launch
// ---------------------------------------------------------------------------
extern "C" void kernel_launch(void* const* d_in, const int* in_sizes, int n_in,
                              void* d_out, int out_size)
{
    const float* x   = (const float*)d_in[0];
    const float* wq  = (const float*)d_in[1];
    const float* wkv = (const float*)d_in[2];
    const float* wo  = (const float*)d_in[3];
    float* out = (float*)d_out;

    float *q, *kv;
    uint32_t *xh, *wqh, *wkvh, *woh, *atth;
    cudaGetSymbolAddress((void**)&q,    g_q);
    cudaGetSymbolAddress((void**)&kv,   g_kv);
    cudaGetSymbolAddress((void**)&xh,   g_xh);
    cudaGetSymbolAddress((void**)&wqh,  g_wqh);
    cudaGetSymbolAddress((void**)&wkvh, g_wkvh);
    cudaGetSymbolAddress((void**)&woh,  g_woh);
    cudaGetSymbolAddress((void**)&atth, g_atth);

    cudaFuncSetAttribute(gemm_fp16,
                         cudaFuncAttributeMaxDynamicSharedMemorySize, GM_SMEM);

    // convert inputs to half
    cvt_half<<<(TOK_ * H_ / 4 + 255) / 256, 256>>>(x, xh, TOK_ * H_ / 4);
    cvt_half<<<(H_ * H_ / 4 + 255) / 256, 256>>>(wq, wqh, H_ * H_ / 4);
    cvt_half<<<(KVW_ * H_ / 4 + 255) / 256, 256>>>(wkv, wkvh, KVW_ * H_ / 4);
    cvt_half<<<(H_ * H_ / 4 + 255) / 256, 256>>>(wo, woh, H_ * H_ / 4);

    // projections
    gemm_fp16<<<dim3(H_ / 128, TOK_ / 128), 128, GM_SMEM>>>(
        (const __half*)xh, (const __half*)wqh, q, TOK_, H_, H_);
    gemm_fp16<<<dim3(KVW_ / 128, TOK_ / 128), 128, GM_SMEM>>>(
        (const __half*)xh, (const __half*)wkvh, kv, TOK_, KVW_, H_);

    // RoPE on Q and K (fp32)
    const int nrope = TOK_ * (NH_ + NKV_) * 32;
    rope_kernel<<<(nrope + 255) / 256, 256>>>(q, kv);

    // causal flash attention -> packed half att
    flash_f16<<<dim3(S_ / 128, B_ * NH_), 128>>>(q, kv, atth);

    // output projection
    gemm_fp16<<<dim3(H_ / 128, TOK_ / 128), 128, GM_SMEM>>>(
        (const __half*)atth, (const __half*)woh, out, TOK_, H_, H_);
}

// round 12
// speedup vs baseline: 2.0076x; 1.1718x over previous
#include <cuda_runtime.h>
#include <cuda_fp16.h>
#include <cstdint>

// ---------------------------------------------------------------------------
// Problem constants
// ---------------------------------------------------------------------------
namespace {
constexpr int B_   = 4;
constexpr int S_   = 2048;
constexpr int H_   = 768;
constexpr int NH_  = 12;
constexpr int NKV_ = 2;
constexpr int HD_  = 64;
constexpr int GRP_ = NH_ / NKV_;      // 6
constexpr int TOK_ = B_ * S_;         // 8192
constexpr int QKVW_ = H_ + 2 * NKV_ * HD_;   // 1024 (q | k | v row width)
}

// ---------------------------------------------------------------------------
// Scratch (static device globals; no allocations allowed)
// ---------------------------------------------------------------------------
__device__ float    g_qkv [TOK_ * QKVW_];          // fp32 q|k|v rows, rope'd
__device__ uint32_t g_xh  [TOK_ * H_ / 2];         // half2-packed x
__device__ uint32_t g_wh  [QKVW_ * H_ / 2];        // wq rows 0..767 | wkv 768..1023
__device__ uint32_t g_woh [H_ * H_ / 2];
__device__ uint32_t g_atth[TOK_ * H_ / 2];         // half2-packed attention output

// ---------------------------------------------------------------------------
// helpers
// ---------------------------------------------------------------------------
__device__ __forceinline__ uint32_t pack_half2(float lo, float hi) {
    uint32_t r;
    asm("cvt.rn.f16x2.f32 %0, %1, %2;" : "=r"(r) : "f"(hi), "f"(lo));
    return r;
}

__device__ __forceinline__ void mma_f16(float c[4], const uint32_t a[4],
                                        uint32_t b0, uint32_t b1) {
    asm volatile(
        "mma.sync.aligned.m16n8k16.row.col.f32.f16.f16.f32 "
        "{%0,%1,%2,%3}, {%4,%5,%6,%7}, {%8,%9}, {%0,%1,%2,%3};\n"
        : "+f"(c[0]), "+f"(c[1]), "+f"(c[2]), "+f"(c[3])
        : "r"(a[0]), "r"(a[1]), "r"(a[2]), "r"(a[3]), "r"(b0), "r"(b1));
}

__device__ __forceinline__ void cp_async16(void* smem_dst, const void* gmem_src) {
    uint32_t sa = (uint32_t)__cvta_generic_to_shared(smem_dst);
    asm volatile("cp.async.ca.shared.global [%0], [%1], 16;\n"
                 :: "r"(sa), "l"(gmem_src));
}
__device__ __forceinline__ void cp_commit() {
    asm volatile("cp.async.commit_group;\n");
}
template <int N>
__device__ __forceinline__ void cp_wait() {
    asm volatile("cp.async.wait_group %0;\n" :: "n"(N));
}

// ---------------------------------------------------------------------------
// One fused fp32 -> half2 convert for all four inputs.
// Regions (in float4 units): x | wq | wkv | wo.  wq+wkv land contiguously in
// g_wh (rows 0..767 = wq, 768..1023 = wkv; both have K=768 so concat is flat).
// ---------------------------------------------------------------------------
namespace {
constexpr int X4_   = TOK_ * H_ / 4;        // 1572864
constexpr int WQ4_  = H_ * H_ / 4;          // 147456
constexpr int WKV4_ = 2 * NKV_ * HD_ * H_ / 4;  // 49152
constexpr int WO4_  = H_ * H_ / 4;          // 147456
constexpr int ALL4_ = X4_ + WQ4_ + WKV4_ + WO4_;
}

__global__ void cvt_all(const float* __restrict__ x,  const float* __restrict__ wq,
                        const float* __restrict__ wkv, const float* __restrict__ wo,
                        uint32_t* __restrict__ xh, uint32_t* __restrict__ wh,
                        uint32_t* __restrict__ woh)
{
    const int i = blockIdx.x * 256 + threadIdx.x;
    if (i >= ALL4_) return;
    const float4* src;
    uint32_t* dst;
    int j = i;
    if (j < X4_)                    { src = (const float4*)x   + j; dst = xh  + j * 2; }
    else if ((j -= X4_)  < WQ4_)    { src = (const float4*)wq  + j; dst = wh  + j * 2; }
    else if ((j -= WQ4_) < WKV4_)   { src = (const float4*)wkv + j; dst = wh  + (WQ4_ + j) * 2; }
    else { j -= WKV4_;                src = (const float4*)wo  + j; dst = woh + j * 2; }
    float4 v = *src;
    dst[0] = pack_half2(v.x, v.y);
    dst[1] = pack_half2(v.z, v.w);
}

// ---------------------------------------------------------------------------
// fp16 GEMM: C[M,N](f32) = A[M,K](half) * B[N,K](half)^T.
// 128x128 tile, BK=32, 128 threads / 4 warps, warp tile 64x64,
// cp.async double-buffered. smem rows = 16 half2 words + 4 pad (stride 20:
// 20*qr+qc and +4 patterns are bank-conflict-free mod 32).
// ---------------------------------------------------------------------------
constexpr int GM_SMEM = 2 * 2 * 128 * 20 * 4;   // 81920 B

__global__ __launch_bounds__(128, 2) void gemm_fp16(
    const __half* __restrict__ A, const __half* __restrict__ B,
    float* __restrict__ C, int M, int N, int K)
{
    extern __shared__ uint32_t GS[];   // As[2][2560] | Bs[2][2560]

    const int tid  = threadIdx.x;
    const int lane = tid & 31;
    const int warp = tid >> 5;
    const int wm   = (warp >> 1) * 64;
    const int wn   = (warp & 1) * 64;
    const int bm   = blockIdx.y * 128;
    const int bn   = blockIdx.x * 128;
    const int qr   = lane >> 2;
    const int qc   = lane & 3;

    float acc[4][8][4];
#pragma unroll
    for (int mt = 0; mt < 4; mt++)
#pragma unroll
        for (int nt = 0; nt < 8; nt++)
#pragma unroll
            for (int i = 0; i < 4; i++) acc[mt][nt][i] = 0.0f;

    const __half* Abase = A + (size_t)bm * K;
    const __half* Bbase = B + (size_t)bn * K;

    auto stage = [&](int buf, int kb) {
        uint32_t* As = GS + buf * 2560;
        uint32_t* Bs = GS + 5120 + buf * 2560;
        const __half* Ab = Abase + kb * 32;
        const __half* Bb = Bbase + kb * 32;
#pragma unroll
        for (int u = 0; u < 4; u++) {
            const int id = tid + u * 128;      // 0..511
            const int r  = id >> 2;
            const int s  = id & 3;
            cp_async16(As + r * 20 + s * 4, Ab + (size_t)r * K + s * 8);
            cp_async16(Bs + r * 20 + s * 4, Bb + (size_t)r * K + s * 8);
        }
    };

    const int nkb = K / 32;
    stage(0, 0);
    cp_commit();

    for (int kb = 0; kb < nkb; kb++) {
        __syncthreads();
        if (kb + 1 < nkb) stage((kb + 1) & 1, kb + 1);
        cp_commit();
        cp_wait<1>();
        __syncthreads();

        const uint32_t* As = GS + (kb & 1) * 2560;
        const uint32_t* Bs = GS + 5120 + (kb & 1) * 2560;

#pragma unroll
        for (int kk = 0; kk < 2; kk++) {
            const int base = kk * 8 + qc;
            uint32_t af[4][4], bf[8][2];
#pragma unroll
            for (int mt = 0; mt < 4; mt++) {
                const int m = wm + mt * 16 + qr;
                af[mt][0] = As[m * 20 + base];
                af[mt][1] = As[(m + 8) * 20 + base];
                af[mt][2] = As[m * 20 + base + 4];
                af[mt][3] = As[(m + 8) * 20 + base + 4];
            }
#pragma unroll
            for (int nt = 0; nt < 8; nt++) {
                const int n = wn + nt * 8 + qr;
                bf[nt][0] = Bs[n * 20 + base];
                bf[nt][1] = Bs[n * 20 + base + 4];
            }
#pragma unroll
            for (int mt = 0; mt < 4; mt++)
#pragma unroll
                for (int nt = 0; nt < 8; nt++)
                    mma_f16(acc[mt][nt], af[mt], bf[nt][0], bf[nt][1]);
        }
    }

#pragma unroll
    for (int mt = 0; mt < 4; mt++) {
        const int m = bm + wm + mt * 16 + qr;
#pragma unroll
        for (int nt = 0; nt < 8; nt++) {
            const int n = bn + wn + nt * 8 + qc * 2;
            *(float2*)&C[(size_t)m * N + n] =
                make_float2(acc[mt][nt][0], acc[mt][nt][1]);
            *(float2*)&C[(size_t)(m + 8) * N + n] =
                make_float2(acc[mt][nt][2], acc[mt][nt][3]);
        }
    }
}

// ---------------------------------------------------------------------------
// RoPE in-place on Q cols [0,768) and K cols [768,896) of qkv rows
// ---------------------------------------------------------------------------
__global__ void rope_kernel(float* __restrict__ qkv)
{
    const int NQ = TOK_ * NH_  * 32;
    const int NK = TOK_ * NKV_ * 32;
    const int i = blockIdx.x * blockDim.x + threadIdx.x;
    if (i >= NQ + NK) return;

    float* base;
    int t, p;
    if (i < NQ) {
        t = i / (NH_ * 32);
        const int r = i % (NH_ * 32);
        const int h = r / 32;
        p = r & 31;
        base = qkv + (size_t)t * QKVW_ + h * HD_;
    } else {
        const int j = i - NQ;
        t = j / (NKV_ * 32);
        const int r = j % (NKV_ * 32);
        const int h = r / 32;
        p = r & 31;
        base = qkv + (size_t)t * QKVW_ + H_ + h * HD_;
    }
    const int s = t & (S_ - 1);
    const float inv = exp2f(-(float)p * 0.41524101186092029f);
    const float ang = (float)s * inv;
    float sn, c;
    __sincosf(ang, &sn, &c);
    const float x0 = base[p], x1 = base[p + 32];
    base[p]      = x0 * c - x1 * sn;
    base[p + 32] = x1 * c + x0 * sn;
}

// ---------------------------------------------------------------------------
// Causal flash attention, fp16 m16n8k16 MMA, 128-query block, 4 warps,
// 32 rows/warp (R11 compute, strides updated for the fused qkv buffer).
//   Ks[key][36 words]: d-pair half2, stride 36 -> 4qr+qc conflict-free.
//   Vs[d][36 words]:   key-pair half2 (d-major) -> PV B-frag natural.
//   P C-frag packs to PV A-frag as half2 of adjacent S columns.
// ---------------------------------------------------------------------------
__global__ __launch_bounds__(128, 2) void flash_f16(
    const float* __restrict__ QKV, uint32_t* __restrict__ Oh)
{
    __shared__ uint32_t Ks[64 * 36];   // 9216 B
    __shared__ uint32_t Vs[64 * 36];   // 9216 B

    const int tid  = threadIdx.x;
    const int lane = tid & 31;
    const int warp = tid >> 5;
    const int qr   = lane >> 2;
    const int qc   = lane & 3;
    const int bh   = blockIdx.y;
    const int b    = bh / NH_;
    const int h    = bh % NH_;
    const int g    = h / GRP_;
    const int m0   = ((int)gridDim.x - 1 - (int)blockIdx.x) * 128;  // heavy first
    const int wrow = warp * 32;

    // ---- stage Q (scaled by log2e/8) as half2 d-pairs into Ks/Vs ----
    const float qs = 0.125f * 1.44269504088896341f;
    for (int i = tid; i < 128 * 16; i += 128) {
        const int r  = i >> 4;
        const int d4 = (i & 15) * 4;
        const float* qp = QKV + (size_t)(b * S_ + m0 + r) * QKVW_ + h * HD_ + d4;
        float4 v = *(const float4*)qp;
        uint32_t* dst = (r < 64) ? &Ks[r * 36 + d4 / 2]
                                 : &Vs[(r - 64) * 36 + d4 / 2];
        dst[0] = pack_half2(v.x * qs, v.y * qs);
        dst[1] = pack_half2(v.z * qs, v.w * qs);
    }
    __syncthreads();

    // qf[mt][kg] = A-frag for k-group kg (d = kg*16 .. kg*16+15)
    uint32_t qf[2][4][4];
#pragma unroll
    for (int mt = 0; mt < 2; mt++) {
        const int rbase = wrow + mt * 16;
        const uint32_t* Qa = (rbase < 64) ? &Ks[rbase * 36]
                                          : &Vs[(rbase - 64) * 36];
#pragma unroll
        for (int kg = 0; kg < 4; kg++) {
            const int c = kg * 8 + qc;
            qf[mt][kg][0] = Qa[qr * 36 + c];
            qf[mt][kg][1] = Qa[(qr + 8) * 36 + c];
            qf[mt][kg][2] = Qa[qr * 36 + c + 4];
            qf[mt][kg][3] = Qa[(qr + 8) * 36 + c + 4];
        }
    }

    float of[2][8][4];
#pragma unroll
    for (int mt = 0; mt < 2; mt++)
#pragma unroll
        for (int dt = 0; dt < 8; dt++)
#pragma unroll
            for (int i = 0; i < 4; i++) of[mt][dt][i] = 0.0f;
    float m_run[2][2] = {{-1e30f, -1e30f}, {-1e30f, -1e30f}};
    float l_run[2][2] = {{0.0f, 0.0f}, {0.0f, 0.0f}};

    const size_t kvbase = (size_t)(b * S_) * QKVW_ + H_ + g * HD_;
    const int ntiles = m0 / 64 + 2;

    for (int kt = 0; kt < ntiles; kt++) {
        const int k0 = kt * 64;
        __syncthreads();
        // K: word(key, dp) = half2(K[key][2dp], K[key][2dp+1])
#pragma unroll
        for (int u = 0; u < 8; u++) {
            const int i   = tid + u * 128;
            const int key = i >> 4;
            const int d4  = (i & 15) * 4;
            float4 k4 = *(const float4*)(QKV + kvbase +
                                         (size_t)(k0 + key) * QKVW_ + d4);
            Ks[key * 36 + d4 / 2]     = pack_half2(k4.x, k4.y);
            Ks[key * 36 + d4 / 2 + 1] = pack_half2(k4.z, k4.w);
        }
        // V: word(d, kp) = half2(V[2kp][d], V[2kp+1][d])  (d-major)
#pragma unroll
        for (int u = 0; u < 16; u++) {
            const int i  = tid + u * 128;
            const int d  = i & 63;
            const int kp = i >> 6;
            const float* vp = QKV + kvbase +
                              (size_t)(k0 + 2 * kp) * QKVW_ + 2 * HD_ + d;
            Vs[d * 36 + kp] = pack_half2(vp[0], vp[QKVW_]);
        }
        __syncthreads();

        if (k0 > m0 + wrow + 31) continue;   // warp fully above the diagonal

        // ---- S = Q K^T (32 x 64 per warp) ----
        float sf[2][8][4];
#pragma unroll
        for (int mt = 0; mt < 2; mt++)
#pragma unroll
            for (int nt = 0; nt < 8; nt++)
#pragma unroll
                for (int i = 0; i < 4; i++) sf[mt][nt][i] = 0.0f;
#pragma unroll
        for (int kg = 0; kg < 4; kg++) {
#pragma unroll
            for (int nh = 0; nh < 2; nh++) {
                uint32_t bfr[4][2];
#pragma unroll
                for (int nt = 0; nt < 4; nt++) {
                    const int n = (nh * 4 + nt) * 8 + qr;
                    bfr[nt][0] = Ks[n * 36 + kg * 8 + qc];
                    bfr[nt][1] = Ks[n * 36 + kg * 8 + qc + 4];
                }
#pragma unroll
                for (int mt = 0; mt < 2; mt++)
#pragma unroll
                    for (int nt = 0; nt < 4; nt++)
                        mma_f16(sf[mt][nh * 4 + nt], qf[mt][kg],
                                bfr[nt][0], bfr[nt][1]);
            }
        }

        // ---- causal mask (diagonal region only) ----
        if (k0 + 63 > m0 + wrow) {
#pragma unroll
            for (int mt = 0; mt < 2; mt++) {
                const int r0 = m0 + wrow + mt * 16 + qr;
#pragma unroll
                for (int nt = 0; nt < 8; nt++) {
                    const int cL = k0 + nt * 8 + qc * 2;
                    if (cL     > r0)     sf[mt][nt][0] = -1e30f;
                    if (cL + 1 > r0)     sf[mt][nt][1] = -1e30f;
                    if (cL     > r0 + 8) sf[mt][nt][2] = -1e30f;
                    if (cL + 1 > r0 + 8) sf[mt][nt][3] = -1e30f;
                }
            }
        }

        // ---- online softmax (exp2 domain); P packed to half2 ----
        uint32_t pp[2][8][2];
#pragma unroll
        for (int mt = 0; mt < 2; mt++) {
            float tm0 = -1e30f, tm1 = -1e30f;
#pragma unroll
            for (int nt = 0; nt < 8; nt++) {
                tm0 = fmaxf(tm0, fmaxf(sf[mt][nt][0], sf[mt][nt][1]));
                tm1 = fmaxf(tm1, fmaxf(sf[mt][nt][2], sf[mt][nt][3]));
            }
            tm0 = fmaxf(tm0, __shfl_xor_sync(0xffffffffu, tm0, 1));
            tm0 = fmaxf(tm0, __shfl_xor_sync(0xffffffffu, tm0, 2));
            tm1 = fmaxf(tm1, __shfl_xor_sync(0xffffffffu, tm1, 1));
            tm1 = fmaxf(tm1, __shfl_xor_sync(0xffffffffu, tm1, 2));

            const float mn0 = fmaxf(m_run[mt][0], tm0);
            const float mn1 = fmaxf(m_run[mt][1], tm1);
            const float cor0 = exp2f(m_run[mt][0] - mn0);
            const float cor1 = exp2f(m_run[mt][1] - mn1);
            m_run[mt][0] = mn0; m_run[mt][1] = mn1;

            float rs0 = 0.0f, rs1 = 0.0f;
#pragma unroll
            for (int nt = 0; nt < 8; nt++) {
                const float p0 = exp2f(sf[mt][nt][0] - mn0);
                const float p1 = exp2f(sf[mt][nt][1] - mn0);
                const float p2 = exp2f(sf[mt][nt][2] - mn1);
                const float p3 = exp2f(sf[mt][nt][3] - mn1);
                rs0 += p0 + p1;
                rs1 += p2 + p3;
                pp[mt][nt][0] = pack_half2(p0, p1);   // row qr,  adjacent keys
                pp[mt][nt][1] = pack_half2(p2, p3);   // row qr+8
            }
            rs0 += __shfl_xor_sync(0xffffffffu, rs0, 1);
            rs0 += __shfl_xor_sync(0xffffffffu, rs0, 2);
            rs1 += __shfl_xor_sync(0xffffffffu, rs1, 1);
            rs1 += __shfl_xor_sync(0xffffffffu, rs1, 2);
            l_run[mt][0] = l_run[mt][0] * cor0 + rs0;
            l_run[mt][1] = l_run[mt][1] * cor1 + rs1;
#pragma unroll
            for (int dt = 0; dt < 8; dt++) {
                of[mt][dt][0] *= cor0; of[mt][dt][1] *= cor0;
                of[mt][dt][2] *= cor1; of[mt][dt][3] *= cor1;
            }
        }

        // ---- O += P V  (A-frag = packed P, identity key order) ----
#pragma unroll
        for (int kg = 0; kg < 4; kg++) {
            uint32_t af[2][4];
#pragma unroll
            for (int mt = 0; mt < 2; mt++) {
                af[mt][0] = pp[mt][2 * kg][0];
                af[mt][1] = pp[mt][2 * kg][1];
                af[mt][2] = pp[mt][2 * kg + 1][0];
                af[mt][3] = pp[mt][2 * kg + 1][1];
            }
#pragma unroll
            for (int dh = 0; dh < 2; dh++) {
                uint32_t vb[4][2];
#pragma unroll
                for (int dt = 0; dt < 4; dt++) {
                    const int d = (dh * 4 + dt) * 8 + qr;
                    vb[dt][0] = Vs[d * 36 + kg * 8 + qc];
                    vb[dt][1] = Vs[d * 36 + kg * 8 + qc + 4];
                }
#pragma unroll
                for (int mt = 0; mt < 2; mt++)
#pragma unroll
                    for (int dt = 0; dt < 4; dt++)
                        mma_f16(of[mt][dh * 4 + dt], af[mt],
                                vb[dt][0], vb[dt][1]);
            }
        }
    }

    // ---- epilogue: write packed half2 att ----
#pragma unroll
    for (int mt = 0; mt < 2; mt++) {
        const float inv0 = 1.0f / l_run[mt][0];
        const float inv1 = 1.0f / l_run[mt][1];
        const int r0 = m0 + wrow + mt * 16 + qr;
#pragma unroll
        for (int dt = 0; dt < 8; dt++) {
            const int col = h * HD_ + dt * 8 + qc * 2;
            Oh[((size_t)(b * S_ + r0) * H_ + col) >> 1] =
                pack_half2(of[mt][dt][0] * inv0, of[mt][dt][1] * inv0);
            Oh[((size_t)(b * S_ + r0 + 8) * H_ + col) >> 1] =
                pack_half2(of[mt][dt][2] * inv1, of[mt][dt][3] * inv1);
        }
    }
}

// ---------------------------------------------------------------------------
// Launch
// ---------------------------------------------------------------------------
extern "C" void kernel_launch(void* const* d_in, const int* in_sizes, int n_in,
                              void* d_out, int out_size)
{
    const float* x   = (const float*)d_in[0];
    const float* wq  = (const float*)d_in[1];
    const float* wkv = (const float*)d_in[2];
    const float* wo  = (const float*)d_in[3];
    float* out = (float*)d_out;

    float* qkv;
    uint32_t *xh, *wh, *woh, *atth;
    cudaGetSymbolAddress((void**)&qkv,  g_qkv);
    cudaGetSymbolAddress((void**)&xh,   g_xh);
    cudaGetSymbolAddress((void**)&wh,   g_wh);
    cudaGetSymbolAddress((void**)&woh,  g_woh);
    cudaGetSymbolAddress((void**)&atth, g_atth);

    cudaFuncSetAttribute(gemm_fp16,
                         cudaFuncAttributeMaxDynamicSharedMemorySize, GM_SMEM);

    // one fused convert: x | wq | wkv -> wh (concat) | wo
    cvt_all<<<(ALL4_ + 255) / 256, 256>>>(x, wq, wkv, wo, xh, wh, woh);

    // fused Q|K|V projection: qkv[8192,1024] = x @ [wq;wkv]^T
    gemm_fp16<<<dim3(QKVW_ / 128, TOK_ / 128), 128, GM_SMEM>>>(
        (const __half*)xh, (const __half*)wh, qkv, TOK_, QKVW_, H_);

    // RoPE on Q and K (fp32, in place)
    const int nrope = TOK_ * (NH_ + NKV_) * 32;
    rope_kernel<<<(nrope + 255) / 256, 256>>>(qkv);

    // causal flash attention -> packed half att
    flash_f16<<<dim3(S_ / 128, B_ * NH_), 128>>>(qkv, atth);

    // output projection
    gemm_fp16<<<dim3(H_ / 128, TOK_ / 128), 128, GM_SMEM>>>(
        (const __half*)atth, (const __half*)woh, out, TOK_, H_, H_);
}

// round 13
// speedup vs baseline: 2.0527x; 1.0225x over previous
#include <cuda_runtime.h>
#include <cuda_fp16.h>
#include <cstdint>

// ---------------------------------------------------------------------------
// Problem constants
// ---------------------------------------------------------------------------
namespace {
constexpr int B_   = 4;
constexpr int S_   = 2048;
constexpr int H_   = 768;
constexpr int NH_  = 12;
constexpr int NKV_ = 2;
constexpr int HD_  = 64;
constexpr int GRP_ = NH_ / NKV_;      // 6
constexpr int TOK_ = B_ * S_;         // 8192
constexpr int QKVW_ = H_ + 2 * NKV_ * HD_;   // 1024 (q | k | v row width)
}

// ---------------------------------------------------------------------------
// Scratch (static device globals; no allocations allowed)
// ---------------------------------------------------------------------------
__device__ float    g_qkv [TOK_ * QKVW_];          // fp32 q|k|v rows, rope'd
__device__ uint32_t g_xh  [TOK_ * H_ / 2];         // half2-packed x
__device__ uint32_t g_wh  [QKVW_ * H_ / 2];        // wq rows 0..767 | wkv 768..1023
__device__ uint32_t g_woh [H_ * H_ / 2];
__device__ uint32_t g_atth[TOK_ * H_ / 2];         // half2-packed attention output

// ---------------------------------------------------------------------------
// helpers
// ---------------------------------------------------------------------------
__device__ __forceinline__ uint32_t pack_half2(float lo, float hi) {
    uint32_t r;
    asm("cvt.rn.f16x2.f32 %0, %1, %2;" : "=r"(r) : "f"(hi), "f"(lo));
    return r;
}

__device__ __forceinline__ float ex2(float x) {   // MUFU exp2, always fast path
    float r;
    asm("ex2.approx.ftz.f32 %0, %1;" : "=f"(r) : "f"(x));
    return r;
}

__device__ __forceinline__ void mma_f16(float c[4], const uint32_t a[4],
                                        uint32_t b0, uint32_t b1) {
    asm volatile(
        "mma.sync.aligned.m16n8k16.row.col.f32.f16.f16.f32 "
        "{%0,%1,%2,%3}, {%4,%5,%6,%7}, {%8,%9}, {%0,%1,%2,%3};\n"
        : "+f"(c[0]), "+f"(c[1]), "+f"(c[2]), "+f"(c[3])
        : "r"(a[0]), "r"(a[1]), "r"(a[2]), "r"(a[3]), "r"(b0), "r"(b1));
}

__device__ __forceinline__ void cp_async16(void* smem_dst, const void* gmem_src) {
    uint32_t sa = (uint32_t)__cvta_generic_to_shared(smem_dst);
    asm volatile("cp.async.ca.shared.global [%0], [%1], 16;\n"
                 :: "r"(sa), "l"(gmem_src));
}
__device__ __forceinline__ void cp_commit() {
    asm volatile("cp.async.commit_group;\n");
}
template <int N>
__device__ __forceinline__ void cp_wait() {
    asm volatile("cp.async.wait_group %0;\n" :: "n"(N));
}

// ---------------------------------------------------------------------------
// One fused fp32 -> half2 convert for all four inputs.
// ---------------------------------------------------------------------------
namespace {
constexpr int X4_   = TOK_ * H_ / 4;
constexpr int WQ4_  = H_ * H_ / 4;
constexpr int WKV4_ = 2 * NKV_ * HD_ * H_ / 4;
constexpr int WO4_  = H_ * H_ / 4;
constexpr int ALL4_ = X4_ + WQ4_ + WKV4_ + WO4_;
}

__global__ void cvt_all(const float* __restrict__ x,  const float* __restrict__ wq,
                        const float* __restrict__ wkv, const float* __restrict__ wo,
                        uint32_t* __restrict__ xh, uint32_t* __restrict__ wh,
                        uint32_t* __restrict__ woh)
{
    const int i = blockIdx.x * 256 + threadIdx.x;
    if (i >= ALL4_) return;
    const float4* src;
    uint32_t* dst;
    int j = i;
    if (j < X4_)                    { src = (const float4*)x   + j; dst = xh  + j * 2; }
    else if ((j -= X4_)  < WQ4_)    { src = (const float4*)wq  + j; dst = wh  + j * 2; }
    else if ((j -= WQ4_) < WKV4_)   { src = (const float4*)wkv + j; dst = wh  + (WQ4_ + j) * 2; }
    else { j -= WKV4_;                src = (const float4*)wo  + j; dst = woh + j * 2; }
    float4 v = *src;
    dst[0] = pack_half2(v.x, v.y);
    dst[1] = pack_half2(v.z, v.w);
}

// ---------------------------------------------------------------------------
// fp16 GEMM: C[M,N](f32) = A[M,K](half) * B[N,K](half)^T.
// 128x128 tile, BK=32, 128 threads / 4 warps, warp tile 64x64,
// cp.async double-buffered, smem stride 20 words (conflict-free).
// ---------------------------------------------------------------------------
constexpr int GM_SMEM = 2 * 2 * 128 * 20 * 4;   // 81920 B

__global__ __launch_bounds__(128, 2) void gemm_fp16(
    const __half* __restrict__ A, const __half* __restrict__ B,
    float* __restrict__ C, int M, int N, int K)
{
    extern __shared__ uint32_t GS[];   // As[2][2560] | Bs[2][2560]

    const int tid  = threadIdx.x;
    const int lane = tid & 31;
    const int warp = tid >> 5;
    const int wm   = (warp >> 1) * 64;
    const int wn   = (warp & 1) * 64;
    const int bm   = blockIdx.y * 128;
    const int bn   = blockIdx.x * 128;
    const int qr   = lane >> 2;
    const int qc   = lane & 3;

    float acc[4][8][4];
#pragma unroll
    for (int mt = 0; mt < 4; mt++)
#pragma unroll
        for (int nt = 0; nt < 8; nt++)
#pragma unroll
            for (int i = 0; i < 4; i++) acc[mt][nt][i] = 0.0f;

    const __half* Abase = A + (size_t)bm * K;
    const __half* Bbase = B + (size_t)bn * K;

    auto stage = [&](int buf, int kb) {
        uint32_t* As = GS + buf * 2560;
        uint32_t* Bs = GS + 5120 + buf * 2560;
        const __half* Ab = Abase + kb * 32;
        const __half* Bb = Bbase + kb * 32;
#pragma unroll
        for (int u = 0; u < 4; u++) {
            const int id = tid + u * 128;      // 0..511
            const int r  = id >> 2;
            const int s  = id & 3;
            cp_async16(As + r * 20 + s * 4, Ab + (size_t)r * K + s * 8);
            cp_async16(Bs + r * 20 + s * 4, Bb + (size_t)r * K + s * 8);
        }
    };

    const int nkb = K / 32;
    stage(0, 0);
    cp_commit();

    for (int kb = 0; kb < nkb; kb++) {
        __syncthreads();
        if (kb + 1 < nkb) stage((kb + 1) & 1, kb + 1);
        cp_commit();
        cp_wait<1>();
        __syncthreads();

        const uint32_t* As = GS + (kb & 1) * 2560;
        const uint32_t* Bs = GS + 5120 + (kb & 1) * 2560;

#pragma unroll
        for (int kk = 0; kk < 2; kk++) {
            const int base = kk * 8 + qc;
            uint32_t af[4][4], bf[8][2];
#pragma unroll
            for (int mt = 0; mt < 4; mt++) {
                const int m = wm + mt * 16 + qr;
                af[mt][0] = As[m * 20 + base];
                af[mt][1] = As[(m + 8) * 20 + base];
                af[mt][2] = As[m * 20 + base + 4];
                af[mt][3] = As[(m + 8) * 20 + base + 4];
            }
#pragma unroll
            for (int nt = 0; nt < 8; nt++) {
                const int n = wn + nt * 8 + qr;
                bf[nt][0] = Bs[n * 20 + base];
                bf[nt][1] = Bs[n * 20 + base + 4];
            }
#pragma unroll
            for (int mt = 0; mt < 4; mt++)
#pragma unroll
                for (int nt = 0; nt < 8; nt++)
                    mma_f16(acc[mt][nt], af[mt], bf[nt][0], bf[nt][1]);
        }
    }

#pragma unroll
    for (int mt = 0; mt < 4; mt++) {
        const int m = bm + wm + mt * 16 + qr;
#pragma unroll
        for (int nt = 0; nt < 8; nt++) {
            const int n = bn + wn + nt * 8 + qc * 2;
            *(float2*)&C[(size_t)m * N + n] =
                make_float2(acc[mt][nt][0], acc[mt][nt][1]);
            *(float2*)&C[(size_t)(m + 8) * N + n] =
                make_float2(acc[mt][nt][2], acc[mt][nt][3]);
        }
    }
}

// ---------------------------------------------------------------------------
// RoPE in-place on Q cols [0,768) and K cols [768,896) of qkv rows
// ---------------------------------------------------------------------------
__global__ void rope_kernel(float* __restrict__ qkv)
{
    const int NQ = TOK_ * NH_  * 32;
    const int NK = TOK_ * NKV_ * 32;
    const int i = blockIdx.x * blockDim.x + threadIdx.x;
    if (i >= NQ + NK) return;

    float* base;
    int t, p;
    if (i < NQ) {
        t = i / (NH_ * 32);
        const int r = i % (NH_ * 32);
        const int h = r / 32;
        p = r & 31;
        base = qkv + (size_t)t * QKVW_ + h * HD_;
    } else {
        const int j = i - NQ;
        t = j / (NKV_ * 32);
        const int r = j % (NKV_ * 32);
        const int h = r / 32;
        p = r & 31;
        base = qkv + (size_t)t * QKVW_ + H_ + h * HD_;
    }
    const int s = t & (S_ - 1);
    const float inv = ex2(-(float)p * 0.41524101186092029f);
    const float ang = (float)s * inv;
    float sn, c;
    __sincosf(ang, &sn, &c);
    const float x0 = base[p], x1 = base[p + 32];
    base[p]      = x0 * c - x1 * sn;
    base[p + 32] = x1 * c + x0 * sn;
}

// ---------------------------------------------------------------------------
// Causal flash attention, fp16 m16n8k16 MMA, 128-query block, 4 warps,
// 32 rows/warp. R13: MUFU ex2 for all exponentials; P half2 bits packed
// back into sf[][][0..1] (no separate pp array -> ~32 fewer live regs).
// ---------------------------------------------------------------------------
__global__ __launch_bounds__(128, 2) void flash_f16(
    const float* __restrict__ QKV, uint32_t* __restrict__ Oh)
{
    __shared__ uint32_t Ks[64 * 36];   // 9216 B
    __shared__ uint32_t Vs[64 * 36];   // 9216 B

    const int tid  = threadIdx.x;
    const int lane = tid & 31;
    const int warp = tid >> 5;
    const int qr   = lane >> 2;
    const int qc   = lane & 3;
    const int bh   = blockIdx.y;
    const int b    = bh / NH_;
    const int h    = bh % NH_;
    const int g    = h / GRP_;
    const int m0   = ((int)gridDim.x - 1 - (int)blockIdx.x) * 128;  // heavy first
    const int wrow = warp * 32;

    // ---- stage Q (scaled by log2e/8) as half2 d-pairs into Ks/Vs ----
    const float qs = 0.125f * 1.44269504088896341f;
    for (int i = tid; i < 128 * 16; i += 128) {
        const int r  = i >> 4;
        const int d4 = (i & 15) * 4;
        const float* qp = QKV + (size_t)(b * S_ + m0 + r) * QKVW_ + h * HD_ + d4;
        float4 v = *(const float4*)qp;
        uint32_t* dst = (r < 64) ? &Ks[r * 36 + d4 / 2]
                                 : &Vs[(r - 64) * 36 + d4 / 2];
        dst[0] = pack_half2(v.x * qs, v.y * qs);
        dst[1] = pack_half2(v.z * qs, v.w * qs);
    }
    __syncthreads();

    uint32_t qf[2][4][4];
#pragma unroll
    for (int mt = 0; mt < 2; mt++) {
        const int rbase = wrow + mt * 16;
        const uint32_t* Qa = (rbase < 64) ? &Ks[rbase * 36]
                                          : &Vs[(rbase - 64) * 36];
#pragma unroll
        for (int kg = 0; kg < 4; kg++) {
            const int c = kg * 8 + qc;
            qf[mt][kg][0] = Qa[qr * 36 + c];
            qf[mt][kg][1] = Qa[(qr + 8) * 36 + c];
            qf[mt][kg][2] = Qa[qr * 36 + c + 4];
            qf[mt][kg][3] = Qa[(qr + 8) * 36 + c + 4];
        }
    }

    float of[2][8][4];
#pragma unroll
    for (int mt = 0; mt < 2; mt++)
#pragma unroll
        for (int dt = 0; dt < 8; dt++)
#pragma unroll
            for (int i = 0; i < 4; i++) of[mt][dt][i] = 0.0f;
    float m_run[2][2] = {{-1e30f, -1e30f}, {-1e30f, -1e30f}};
    float l_run[2][2] = {{0.0f, 0.0f}, {0.0f, 0.0f}};

    const size_t kvbase = (size_t)(b * S_) * QKVW_ + H_ + g * HD_;
    const int ntiles = m0 / 64 + 2;

    for (int kt = 0; kt < ntiles; kt++) {
        const int k0 = kt * 64;
        __syncthreads();
#pragma unroll
        for (int u = 0; u < 8; u++) {
            const int i   = tid + u * 128;
            const int key = i >> 4;
            const int d4  = (i & 15) * 4;
            float4 k4 = *(const float4*)(QKV + kvbase +
                                         (size_t)(k0 + key) * QKVW_ + d4);
            Ks[key * 36 + d4 / 2]     = pack_half2(k4.x, k4.y);
            Ks[key * 36 + d4 / 2 + 1] = pack_half2(k4.z, k4.w);
        }
#pragma unroll
        for (int u = 0; u < 16; u++) {
            const int i  = tid + u * 128;
            const int d  = i & 63;
            const int kp = i >> 6;
            const float* vp = QKV + kvbase +
                              (size_t)(k0 + 2 * kp) * QKVW_ + 2 * HD_ + d;
            Vs[d * 36 + kp] = pack_half2(vp[0], vp[QKVW_]);
        }
        __syncthreads();

        if (k0 > m0 + wrow + 31) continue;   // warp fully above the diagonal

        // ---- S = Q K^T (32 x 64 per warp) ----
        float sf[2][8][4];
#pragma unroll
        for (int mt = 0; mt < 2; mt++)
#pragma unroll
            for (int nt = 0; nt < 8; nt++)
#pragma unroll
                for (int i = 0; i < 4; i++) sf[mt][nt][i] = 0.0f;
#pragma unroll
        for (int kg = 0; kg < 4; kg++) {
#pragma unroll
            for (int nh = 0; nh < 2; nh++) {
                uint32_t bfr[4][2];
#pragma unroll
                for (int nt = 0; nt < 4; nt++) {
                    const int n = (nh * 4 + nt) * 8 + qr;
                    bfr[nt][0] = Ks[n * 36 + kg * 8 + qc];
                    bfr[nt][1] = Ks[n * 36 + kg * 8 + qc + 4];
                }
#pragma unroll
                for (int mt = 0; mt < 2; mt++)
#pragma unroll
                    for (int nt = 0; nt < 4; nt++)
                        mma_f16(sf[mt][nh * 4 + nt], qf[mt][kg],
                                bfr[nt][0], bfr[nt][1]);
            }
        }

        // ---- causal mask (diagonal region only) ----
        if (k0 + 63 > m0 + wrow) {
#pragma unroll
            for (int mt = 0; mt < 2; mt++) {
                const int r0 = m0 + wrow + mt * 16 + qr;
#pragma unroll
                for (int nt = 0; nt < 8; nt++) {
                    const int cL = k0 + nt * 8 + qc * 2;
                    if (cL     > r0)     sf[mt][nt][0] = -1e30f;
                    if (cL + 1 > r0)     sf[mt][nt][1] = -1e30f;
                    if (cL     > r0 + 8) sf[mt][nt][2] = -1e30f;
                    if (cL + 1 > r0 + 8) sf[mt][nt][3] = -1e30f;
                }
            }
        }

        // ---- online softmax (MUFU ex2); P half2 bits packed into sf ----
#pragma unroll
        for (int mt = 0; mt < 2; mt++) {
            float tm0 = -1e30f, tm1 = -1e30f;
#pragma unroll
            for (int nt = 0; nt < 8; nt++) {
                tm0 = fmaxf(tm0, fmaxf(sf[mt][nt][0], sf[mt][nt][1]));
                tm1 = fmaxf(tm1, fmaxf(sf[mt][nt][2], sf[mt][nt][3]));
            }
            tm0 = fmaxf(tm0, __shfl_xor_sync(0xffffffffu, tm0, 1));
            tm0 = fmaxf(tm0, __shfl_xor_sync(0xffffffffu, tm0, 2));
            tm1 = fmaxf(tm1, __shfl_xor_sync(0xffffffffu, tm1, 1));
            tm1 = fmaxf(tm1, __shfl_xor_sync(0xffffffffu, tm1, 2));

            const float mn0 = fmaxf(m_run[mt][0], tm0);
            const float mn1 = fmaxf(m_run[mt][1], tm1);
            const float cor0 = ex2(m_run[mt][0] - mn0);
            const float cor1 = ex2(m_run[mt][1] - mn1);
            m_run[mt][0] = mn0; m_run[mt][1] = mn1;

            float rs0 = 0.0f, rs1 = 0.0f;
#pragma unroll
            for (int nt = 0; nt < 8; nt++) {
                const float p0 = ex2(sf[mt][nt][0] - mn0);
                const float p1 = ex2(sf[mt][nt][1] - mn0);
                const float p2 = ex2(sf[mt][nt][2] - mn1);
                const float p3 = ex2(sf[mt][nt][3] - mn1);
                rs0 += p0 + p1;
                rs1 += p2 + p3;
                sf[mt][nt][0] = __uint_as_float(pack_half2(p0, p1));
                sf[mt][nt][1] = __uint_as_float(pack_half2(p2, p3));
            }
            rs0 += __shfl_xor_sync(0xffffffffu, rs0, 1);
            rs0 += __shfl_xor_sync(0xffffffffu, rs0, 2);
            rs1 += __shfl_xor_sync(0xffffffffu, rs1, 1);
            rs1 += __shfl_xor_sync(0xffffffffu, rs1, 2);
            l_run[mt][0] = l_run[mt][0] * cor0 + rs0;
            l_run[mt][1] = l_run[mt][1] * cor1 + rs1;
#pragma unroll
            for (int dt = 0; dt < 8; dt++) {
                of[mt][dt][0] *= cor0; of[mt][dt][1] *= cor0;
                of[mt][dt][2] *= cor1; of[mt][dt][3] *= cor1;
            }
        }

        // ---- O += P V  (A-frag = packed P bits from sf) ----
#pragma unroll
        for (int kg = 0; kg < 4; kg++) {
            uint32_t af[2][4];
#pragma unroll
            for (int mt = 0; mt < 2; mt++) {
                af[mt][0] = __float_as_uint(sf[mt][2 * kg][0]);
                af[mt][1] = __float_as_uint(sf[mt][2 * kg][1]);
                af[mt][2] = __float_as_uint(sf[mt][2 * kg + 1][0]);
                af[mt][3] = __float_as_uint(sf[mt][2 * kg + 1][1]);
            }
#pragma unroll
            for (int dh = 0; dh < 2; dh++) {
                uint32_t vb[4][2];
#pragma unroll
                for (int dt = 0; dt < 4; dt++) {
                    const int d = (dh * 4 + dt) * 8 + qr;
                    vb[dt][0] = Vs[d * 36 + kg * 8 + qc];
                    vb[dt][1] = Vs[d * 36 + kg * 8 + qc + 4];
                }
#pragma unroll
                for (int mt = 0; mt < 2; mt++)
#pragma unroll
                    for (int dt = 0; dt < 4; dt++)
                        mma_f16(of[mt][dh * 4 + dt], af[mt],
                                vb[dt][0], vb[dt][1]);
            }
        }
    }

    // ---- epilogue: write packed half2 att ----
#pragma unroll
    for (int mt = 0; mt < 2; mt++) {
        const float inv0 = 1.0f / l_run[mt][0];
        const float inv1 = 1.0f / l_run[mt][1];
        const int r0 = m0 + wrow + mt * 16 + qr;
#pragma unroll
        for (int dt = 0; dt < 8; dt++) {
            const int col = h * HD_ + dt * 8 + qc * 2;
            Oh[((size_t)(b * S_ + r0) * H_ + col) >> 1] =
                pack_half2(of[mt][dt][0] * inv0, of[mt][dt][1] * inv0);
            Oh[((size_t)(b * S_ + r0 + 8) * H_ + col) >> 1] =
                pack_half2(of[mt][dt][2] * inv1, of[mt][dt][3] * inv1);
        }
    }
}

// ---------------------------------------------------------------------------
// Launch
// ---------------------------------------------------------------------------
extern "C" void kernel_launch(void* const* d_in, const int* in_sizes, int n_in,
                              void* d_out, int out_size)
{
    const float* x   = (const float*)d_in[0];
    const float* wq  = (const float*)d_in[1];
    const float* wkv = (const float*)d_in[2];
    const float* wo  = (const float*)d_in[3];
    float* out = (float*)d_out;

    float* qkv;
    uint32_t *xh, *wh, *woh, *atth;
    cudaGetSymbolAddress((void**)&qkv,  g_qkv);
    cudaGetSymbolAddress((void**)&xh,   g_xh);
    cudaGetSymbolAddress((void**)&wh,   g_wh);
    cudaGetSymbolAddress((void**)&woh,  g_woh);
    cudaGetSymbolAddress((void**)&atth, g_atth);

    cudaFuncSetAttribute(gemm_fp16,
                         cudaFuncAttributeMaxDynamicSharedMemorySize, GM_SMEM);

    cvt_all<<<(ALL4_ + 255) / 256, 256>>>(x, wq, wkv, wo, xh, wh, woh);

    gemm_fp16<<<dim3(QKVW_ / 128, TOK_ / 128), 128, GM_SMEM>>>(
        (const __half*)xh, (const __half*)wh, qkv, TOK_, QKVW_, H_);

    const int nrope = TOK_ * (NH_ + NKV_) * 32;
    rope_kernel<<<(nrope + 255) / 256, 256>>>(qkv);

    flash_f16<<<dim3(S_ / 128, B_ * NH_), 128>>>(qkv, atth);

    gemm_fp16<<<dim3(H_ / 128, TOK_ / 128), 128, GM_SMEM>>>(
        (const __half*)atth, (const __half*)woh, out, TOK_, H_, H_);
}